// round 8
// baseline (speedup 1.0000x reference)
#include <cuda_runtime.h>
#include <cuda_bf16.h>
#include <cstddef>

// ---------------- problem constants ----------------
#define BATCH 2
#define TSEQ  1024
#define MROWS (BATCH*TSEQ)      // 2048
#define DMODEL 768
#define NHEAD 12
#define DHEAD 64
#define DMLP  3072
#define NLAYER 12
#define VOCAB 50257

// ---------------- scratch (static device globals; no allocation) ----------------
__device__ float g_x [MROWS*DMODEL];   // residual stream
__device__ float g_h [MROWS*DMODEL];   // LN output
__device__ float g_q [MROWS*DMODEL];
__device__ float g_k [MROWS*DMODEL];
__device__ float g_v [MROWS*DMODEL];
__device__ float g_z [MROWS*DMODEL];   // attention output (pre-proj)
__device__ float g_m [MROWS*DMLP];     // MLP hidden

// ---------------- helpers ----------------
__device__ __forceinline__ float gelu_f(float x){
    // exact GELU: 0.5*x*(1+erf(x/sqrt(2))) — matches jax.nn.gelu(approximate=False)
    return 0.5f * x * (1.0f + erff(x * 0.70710678118654752440f));
}

// ---------------- embedding: x = emb[ids] + pos ----------------
__global__ void embed_k(const int* __restrict__ ids,
                        const float* __restrict__ emb,
                        const float* __restrict__ pos,
                        float* __restrict__ x)
{
    int row = blockIdx.x;                 // b*T + t
    int t   = row % TSEQ;
    int id  = ids[row];
    const float* er = emb + (size_t)id * DMODEL;
    const float* pr = pos + (size_t)t  * DMODEL;
    float* xr = x + (size_t)row * DMODEL;
    int tid = threadIdx.x;                // 256 threads, 3 elems each
    xr[tid]       = er[tid]       + pr[tid];
    xr[tid + 256] = er[tid + 256] + pr[tid + 256];
    xr[tid + 512] = er[tid + 512] + pr[tid + 512];
}

// ---------------- layernorm: one block (256 thr) per row, D=768 ----------------
__global__ void ln_k(const float* __restrict__ x,
                     const float* __restrict__ g,
                     const float* __restrict__ b,
                     float* __restrict__ out)
{
    __shared__ float red0[8], red1[8];
    int row = blockIdx.x, tid = threadIdx.x;
    const float* xr = x + (size_t)row * DMODEL;
    float v0 = xr[tid], v1 = xr[tid + 256], v2 = xr[tid + 512];
    float s  = v0 + v1 + v2;
    float s2 = v0*v0 + v1*v1 + v2*v2;
    #pragma unroll
    for (int off = 16; off; off >>= 1){
        s  += __shfl_xor_sync(0xffffffffu, s,  off);
        s2 += __shfl_xor_sync(0xffffffffu, s2, off);
    }
    int w = tid >> 5;
    if ((tid & 31) == 0){ red0[w] = s; red1[w] = s2; }
    __syncthreads();
    if (tid < 32){
        s  = (tid < 8) ? red0[tid] : 0.f;
        s2 = (tid < 8) ? red1[tid] : 0.f;
        #pragma unroll
        for (int off = 4; off; off >>= 1){
            s  += __shfl_xor_sync(0xffffffffu, s,  off);
            s2 += __shfl_xor_sync(0xffffffffu, s2, off);
        }
        if (tid == 0){ red0[0] = s; red1[0] = s2; }
    }
    __syncthreads();
    float mean = red0[0] * (1.f/768.f);
    float var  = red1[0] * (1.f/768.f) - mean * mean;
    float r    = rsqrtf(var + 1e-5f);
    float* orow = out + (size_t)row * DMODEL;
    orow[tid]       = (v0 - mean) * r * g[tid]       + b[tid];
    orow[tid + 256] = (v1 - mean) * r * g[tid + 256] + b[tid + 256];
    orow[tid + 512] = (v2 - mean) * r * g[tid + 512] + b[tid + 512];
}

// ---------------- tiled fp32 GEMM:  C = epi(A[M,K] * B[K,N] + bias) ----------------
// EPI: 0 = none, 1 = GELU, 2 = add residual (res[M,N])
template<int BM, int BN, int BK, int TM, int TN, int EPI>
__global__ void gemm_k(const float* __restrict__ A, const float* __restrict__ B,
                       const float* __restrict__ bias, const float* res,
                       float* C, int M, int N, int K)
{
    __shared__ float As[BK][BM];
    __shared__ float Bs[BK][BN];
    constexpr int NT = 256;
    const int tid = threadIdx.x;
    const int tx  = tid % (BN / TN);
    const int ty  = tid / (BN / TN);
    const int m0  = blockIdx.y * BM;
    const int n0  = blockIdx.x * BN;

    float acc[TM][TN];
    #pragma unroll
    for (int i = 0; i < TM; i++)
        #pragma unroll
        for (int j = 0; j < TN; j++) acc[i][j] = 0.f;

    const bool nvec = ((N & 3) == 0);

    for (int k0 = 0; k0 < K; k0 += BK){
        // load A tile (transposed into As[k][m]); M, K multiples of tile dims
        #pragma unroll
        for (int it = 0; it < (BM * BK) / (NT * 4); ++it){
            int e = (it * NT + tid) * 4;
            int r = e / BK, c = e % BK;
            float4 a4 = *(const float4*)(A + (size_t)(m0 + r) * K + k0 + c);
            As[c + 0][r] = a4.x; As[c + 1][r] = a4.y;
            As[c + 2][r] = a4.z; As[c + 3][r] = a4.w;
        }
        // load B tile (N may be ragged / unaligned, e.g. vocab=50257)
        #pragma unroll
        for (int it = 0; it < (BK * BN) / (NT * 4); ++it){
            int e = (it * NT + tid) * 4;
            int r = e / BN, c = e % BN;
            int gn = n0 + c;
            float4 b4;
            if (nvec && gn + 3 < N){
                b4 = *(const float4*)(B + (size_t)(k0 + r) * N + gn);
            } else {
                const float* bp = B + (size_t)(k0 + r) * N;
                b4.x = (gn + 0 < N) ? bp[gn + 0] : 0.f;
                b4.y = (gn + 1 < N) ? bp[gn + 1] : 0.f;
                b4.z = (gn + 2 < N) ? bp[gn + 2] : 0.f;
                b4.w = (gn + 3 < N) ? bp[gn + 3] : 0.f;
            }
            *(float4*)&Bs[r][c] = b4;
        }
        __syncthreads();
        #pragma unroll
        for (int kk = 0; kk < BK; ++kk){
            float ra[TM], rb[TN];
            #pragma unroll
            for (int i = 0; i < TM; i += 4)
                *(float4*)&ra[i] = *(const float4*)&As[kk][ty * TM + i];
            #pragma unroll
            for (int j = 0; j < TN; j += 4)
                *(float4*)&rb[j] = *(const float4*)&Bs[kk][tx * TN + j];
            #pragma unroll
            for (int i = 0; i < TM; i++)
                #pragma unroll
                for (int j = 0; j < TN; j++)
                    acc[i][j] = fmaf(ra[i], rb[j], acc[i][j]);
        }
        __syncthreads();
    }

    #pragma unroll
    for (int i = 0; i < TM; i++){
        int m = m0 + ty * TM + i;
        #pragma unroll
        for (int j = 0; j < TN; j++){
            int n = n0 + tx * TN + j;
            if (n < N){
                float v = acc[i][j] + bias[n];
                if (EPI == 1) v = gelu_f(v);
                if (EPI == 2) v += res[(size_t)m * N + n];
                C[(size_t)m * N + n] = v;
            }
        }
    }
}

// ---------------- fused causal attention (flash-style, fp32) ----------------
// One block per (b*h, 64-row q tile). 256 threads as 16x16.
// smem: Qt (Q^T), Kt (K^T, later aliased as P[q][k]), Vs -> exactly 48 KB.
__global__ void attn_k(const float* __restrict__ Qg, const float* __restrict__ Kg,
                       const float* __restrict__ Vg, float* __restrict__ Og)
{
    __shared__ float Qt[64][64];   // Qt[d][q]
    __shared__ float Kt[64][64];   // Kt[d][k]; reused as P[q][k]
    __shared__ float Vs[64][64];   // Vs[k][d]

    const int tid = threadIdx.x;
    const int tx  = tid & 15, ty = tid >> 4;
    const int bh  = blockIdx.y;
    const int b   = bh / NHEAD, h = bh % NHEAD;
    const int q0  = blockIdx.x * 64;
    const size_t base = (size_t)b * TSEQ * DMODEL + (size_t)h * DHEAD;

    // load Q tile transposed
    #pragma unroll
    for (int it = 0; it < 4; ++it){
        int e = (it * 256 + tid) * 4;
        int r = e >> 6, c = e & 63;
        float4 q4 = *(const float4*)(Qg + base + (size_t)(q0 + r) * DMODEL + c);
        Qt[c + 0][r] = q4.x; Qt[c + 1][r] = q4.y;
        Qt[c + 2][r] = q4.z; Qt[c + 3][r] = q4.w;
    }

    float m_i[4], l_i[4], o[4][4];
    #pragma unroll
    for (int i = 0; i < 4; i++){
        m_i[i] = -1e30f; l_i[i] = 0.f;
        #pragma unroll
        for (int j = 0; j < 4; j++) o[i][j] = 0.f;
    }

    const int nkt = blockIdx.x + 1;          // causal: only tiles with k0 <= q0
    for (int kt = 0; kt < nkt; ++kt){
        const int k0 = kt * 64;
        __syncthreads();                     // protect Kt/Vs (and Qt on first iter)
        #pragma unroll
        for (int it = 0; it < 4; ++it){
            int e = (it * 256 + tid) * 4;
            int r = e >> 6, c = e & 63;
            float4 k4 = *(const float4*)(Kg + base + (size_t)(k0 + r) * DMODEL + c);
            Kt[c + 0][r] = k4.x; Kt[c + 1][r] = k4.y;
            Kt[c + 2][r] = k4.z; Kt[c + 3][r] = k4.w;
            *(float4*)&Vs[r][c] = *(const float4*)(Vg + base + (size_t)(k0 + r) * DMODEL + c);
        }
        __syncthreads();

        // S = Q K^T
        float s[4][4];
        #pragma unroll
        for (int i = 0; i < 4; i++)
            #pragma unroll
            for (int j = 0; j < 4; j++) s[i][j] = 0.f;
        #pragma unroll 16
        for (int d = 0; d < 64; ++d){
            float qa[4], kb[4];
            *(float4*)qa = *(const float4*)&Qt[d][ty * 4];
            *(float4*)kb = *(const float4*)&Kt[d][tx * 4];
            #pragma unroll
            for (int i = 0; i < 4; i++)
                #pragma unroll
                for (int j = 0; j < 4; j++)
                    s[i][j] = fmaf(qa[i], kb[j], s[i][j]);
        }

        // scale + causal mask
        #pragma unroll
        for (int i = 0; i < 4; i++){
            int qg = q0 + ty * 4 + i;
            #pragma unroll
            for (int j = 0; j < 4; j++){
                int kg = k0 + tx * 4 + j;
                s[i][j] = (kg <= qg) ? s[i][j] * 0.125f : -1e30f;
            }
        }

        // online softmax (row reductions over the 16 tx lanes)
        float corr[4];
        #pragma unroll
        for (int i = 0; i < 4; i++){
            float mloc = fmaxf(fmaxf(s[i][0], s[i][1]), fmaxf(s[i][2], s[i][3]));
            #pragma unroll
            for (int off = 8; off; off >>= 1)
                mloc = fmaxf(mloc, __shfl_xor_sync(0xffffffffu, mloc, off, 16));
            float mn = fmaxf(m_i[i], mloc);
            corr[i] = expf(m_i[i] - mn);
            m_i[i]  = mn;
            float rs = 0.f;
            #pragma unroll
            for (int j = 0; j < 4; j++){
                float p = expf(s[i][j] - mn);   // masked -> exp(-huge) = 0
                s[i][j] = p;
                rs += p;
            }
            #pragma unroll
            for (int off = 8; off; off >>= 1)
                rs += __shfl_xor_sync(0xffffffffu, rs, off, 16);
            l_i[i] = l_i[i] * corr[i] + rs;
            #pragma unroll
            for (int j = 0; j < 4; j++) o[i][j] *= corr[i];
        }

        __syncthreads();                     // everyone done reading Kt as K^T
        #pragma unroll
        for (int i = 0; i < 4; i++)
            #pragma unroll
            for (int j = 0; j < 4; j++)
                Kt[ty * 4 + i][tx * 4 + j] = s[i][j];   // P[q][k]
        __syncthreads();

        // O += P V
        #pragma unroll 16
        for (int k = 0; k < 64; ++k){
            float vb[4];
            *(float4*)vb = *(const float4*)&Vs[k][tx * 4];
            #pragma unroll
            for (int i = 0; i < 4; i++){
                float p = Kt[ty * 4 + i][k];
                #pragma unroll
                for (int j = 0; j < 4; j++)
                    o[i][j] = fmaf(p, vb[j], o[i][j]);
            }
        }
    }

    // normalize + store
    #pragma unroll
    for (int i = 0; i < 4; i++){
        float inv = 1.f / l_i[i];
        int qg = q0 + ty * 4 + i;
        float4 r4 = make_float4(o[i][0]*inv, o[i][1]*inv, o[i][2]*inv, o[i][3]*inv);
        *(float4*)(Og + base + (size_t)qg * DMODEL + tx * 4) = r4;
    }
}

// ---------------- host orchestration ----------------
extern "C" void kernel_launch(void* const* d_in, const int* in_sizes, int n_in,
                              void* d_out, int out_size)
{
    const int*   ids = (const int*)  d_in[0];
    const float* emb = (const float*)d_in[1];
    const float* pos = (const float*)d_in[2];
    const float* Wq  = (const float*)d_in[3],  *bq = (const float*)d_in[4];
    const float* Wk  = (const float*)d_in[5],  *bk = (const float*)d_in[6];
    const float* Wv  = (const float*)d_in[7],  *bv = (const float*)d_in[8];
    const float* Wo  = (const float*)d_in[9],  *bo = (const float*)d_in[10];
    const float* l1g = (const float*)d_in[11], *l1b = (const float*)d_in[12];
    const float* l2g = (const float*)d_in[13], *l2b = (const float*)d_in[14];
    const float* W1  = (const float*)d_in[15], *b1 = (const float*)d_in[16];
    const float* W2  = (const float*)d_in[17], *b2 = (const float*)d_in[18];
    const float* lfg = (const float*)d_in[19], *lfb = (const float*)d_in[20];
    const float* Wu  = (const float*)d_in[21], *bu = (const float*)d_in[22];
    float* out = (float*)d_out;

    float *x, *h, *q, *k, *v, *z, *mm;
    cudaGetSymbolAddress((void**)&x,  g_x);
    cudaGetSymbolAddress((void**)&h,  g_h);
    cudaGetSymbolAddress((void**)&q,  g_q);
    cudaGetSymbolAddress((void**)&k,  g_k);
    cudaGetSymbolAddress((void**)&v,  g_v);
    cudaGetSymbolAddress((void**)&z,  g_z);
    cudaGetSymbolAddress((void**)&mm, g_m);

    const int M = MROWS, D = DMODEL, DM = DMLP, Vn = VOCAB;
    dim3 g64(D / 64, M / 64);                       // (12, 32)

    embed_k<<<M, 256>>>(ids, emb, pos, x);

    for (int l = 0; l < NLAYER; ++l){
        const size_t oD2 = (size_t)l * D * D;
        ln_k<<<M, 256>>>(x, l1g + l * D, l1b + l * D, h);
        gemm_k<64,64,16,4,4,0><<<g64, 256>>>(h, Wq + oD2, bq + l * D, nullptr, q, M, D, D);
        gemm_k<64,64,16,4,4,0><<<g64, 256>>>(h, Wk + oD2, bk + l * D, nullptr, k, M, D, D);
        gemm_k<64,64,16,4,4,0><<<g64, 256>>>(h, Wv + oD2, bv + l * D, nullptr, v, M, D, D);
        attn_k<<<dim3(TSEQ / 64, BATCH * NHEAD), 256>>>(q, k, v, z);
        gemm_k<64,64,16,4,4,2><<<g64, 256>>>(z, Wo + oD2, bo + l * D, x, x, M, D, D);
        ln_k<<<M, 256>>>(x, l2g + l * D, l2b + l * D, h);
        gemm_k<128,128,16,8,8,1><<<dim3(DM / 128, M / 128), 256>>>(
            h, W1 + (size_t)l * D * DM, b1 + l * DM, nullptr, mm, M, DM, D);
        gemm_k<64,64,16,4,4,2><<<g64, 256>>>(mm, W2 + (size_t)l * DM * D, b2 + l * D, x, x, M, D, DM);
    }

    ln_k<<<M, 256>>>(x, lfg, lfb, h);
    gemm_k<128,128,16,8,8,0><<<dim3((Vn + 127) / 128, M / 128), 256>>>(
        h, Wu, bu, nullptr, out, M, Vn, D);
}

// round 9
// speedup vs baseline: 1.0019x; 1.0019x over previous
#include <cuda_runtime.h>
#include <cuda_bf16.h>
#include <cstddef>

// ---------------- problem constants ----------------
#define BATCH 2
#define TSEQ  1024
#define MROWS (BATCH*TSEQ)      // 2048
#define DMODEL 768
#define NHEAD 12
#define DHEAD 64
#define DMLP  3072
#define NLAYER 12
#define VOCAB 50257

// ---------------- scratch (static device globals; no allocation) ----------------
__device__ float g_x [MROWS*DMODEL];   // residual stream
__device__ float g_h [MROWS*DMODEL];   // LN output
__device__ float g_q [MROWS*DMODEL];
__device__ float g_k [MROWS*DMODEL];
__device__ float g_v [MROWS*DMODEL];
__device__ float g_z [MROWS*DMODEL];   // attention output (pre-proj)
__device__ float g_m [MROWS*DMLP];     // MLP hidden

// ---------------- helpers ----------------
__device__ __forceinline__ float gelu_f(float x){
    // exact GELU: 0.5*x*(1+erf(x/sqrt(2))) — matches jax.nn.gelu(approximate=False)
    return 0.5f * x * (1.0f + erff(x * 0.70710678118654752440f));
}

// ---------------- embedding: x = emb[ids] + pos ----------------
__global__ void embed_k(const int* __restrict__ ids,
                        const float* __restrict__ emb,
                        const float* __restrict__ pos,
                        float* __restrict__ x)
{
    int row = blockIdx.x;                 // b*T + t
    int t   = row % TSEQ;
    int id  = ids[row];
    const float* er = emb + (size_t)id * DMODEL;
    const float* pr = pos + (size_t)t  * DMODEL;
    float* xr = x + (size_t)row * DMODEL;
    int tid = threadIdx.x;                // 256 threads, 3 elems each
    xr[tid]       = er[tid]       + pr[tid];
    xr[tid + 256] = er[tid + 256] + pr[tid + 256];
    xr[tid + 512] = er[tid + 512] + pr[tid + 512];
}

// ---------------- layernorm: one block (256 thr) per row, D=768 ----------------
__global__ void ln_k(const float* __restrict__ x,
                     const float* __restrict__ g,
                     const float* __restrict__ b,
                     float* __restrict__ out)
{
    __shared__ float red0[8], red1[8];
    int row = blockIdx.x, tid = threadIdx.x;
    const float* xr = x + (size_t)row * DMODEL;
    float v0 = xr[tid], v1 = xr[tid + 256], v2 = xr[tid + 512];
    float s  = v0 + v1 + v2;
    float s2 = v0*v0 + v1*v1 + v2*v2;
    #pragma unroll
    for (int off = 16; off; off >>= 1){
        s  += __shfl_xor_sync(0xffffffffu, s,  off);
        s2 += __shfl_xor_sync(0xffffffffu, s2, off);
    }
    int w = tid >> 5;
    if ((tid & 31) == 0){ red0[w] = s; red1[w] = s2; }
    __syncthreads();
    if (tid < 32){
        s  = (tid < 8) ? red0[tid] : 0.f;
        s2 = (tid < 8) ? red1[tid] : 0.f;
        #pragma unroll
        for (int off = 4; off; off >>= 1){
            s  += __shfl_xor_sync(0xffffffffu, s,  off);
            s2 += __shfl_xor_sync(0xffffffffu, s2, off);
        }
        if (tid == 0){ red0[0] = s; red1[0] = s2; }
    }
    __syncthreads();
    float mean = red0[0] * (1.f/768.f);
    float var  = red1[0] * (1.f/768.f) - mean * mean;
    float r    = rsqrtf(var + 1e-5f);
    float* orow = out + (size_t)row * DMODEL;
    orow[tid]       = (v0 - mean) * r * g[tid]       + b[tid];
    orow[tid + 256] = (v1 - mean) * r * g[tid + 256] + b[tid + 256];
    orow[tid + 512] = (v2 - mean) * r * g[tid + 512] + b[tid + 512];
}

// ---------------- tiled fp32 GEMM:  C = epi(A[M,K] * B[K,N] + bias) ----------------
// EPI: 0 = none, 1 = GELU, 2 = add residual (res[M,N])
template<int BM, int BN, int BK, int TM, int TN, int EPI>
__global__ void gemm_k(const float* __restrict__ A, const float* __restrict__ B,
                       const float* __restrict__ bias, const float* res,
                       float* C, int M, int N, int K)
{
    __shared__ float As[BK][BM];
    __shared__ float Bs[BK][BN];
    constexpr int NT = 256;
    const int tid = threadIdx.x;
    const int tx  = tid % (BN / TN);
    const int ty  = tid / (BN / TN);
    const int m0  = blockIdx.y * BM;
    const int n0  = blockIdx.x * BN;

    float acc[TM][TN];
    #pragma unroll
    for (int i = 0; i < TM; i++)
        #pragma unroll
        for (int j = 0; j < TN; j++) acc[i][j] = 0.f;

    const bool nvec = ((N & 3) == 0);

    for (int k0 = 0; k0 < K; k0 += BK){
        // load A tile (transposed into As[k][m]); M, K multiples of tile dims
        #pragma unroll
        for (int it = 0; it < (BM * BK) / (NT * 4); ++it){
            int e = (it * NT + tid) * 4;
            int r = e / BK, c = e % BK;
            float4 a4 = *(const float4*)(A + (size_t)(m0 + r) * K + k0 + c);
            As[c + 0][r] = a4.x; As[c + 1][r] = a4.y;
            As[c + 2][r] = a4.z; As[c + 3][r] = a4.w;
        }
        // load B tile (N may be ragged / unaligned, e.g. vocab=50257)
        #pragma unroll
        for (int it = 0; it < (BK * BN) / (NT * 4); ++it){
            int e = (it * NT + tid) * 4;
            int r = e / BN, c = e % BN;
            int gn = n0 + c;
            float4 b4;
            if (nvec && gn + 3 < N){
                b4 = *(const float4*)(B + (size_t)(k0 + r) * N + gn);
            } else {
                const float* bp = B + (size_t)(k0 + r) * N;
                b4.x = (gn + 0 < N) ? bp[gn + 0] : 0.f;
                b4.y = (gn + 1 < N) ? bp[gn + 1] : 0.f;
                b4.z = (gn + 2 < N) ? bp[gn + 2] : 0.f;
                b4.w = (gn + 3 < N) ? bp[gn + 3] : 0.f;
            }
            *(float4*)&Bs[r][c] = b4;
        }
        __syncthreads();
        #pragma unroll
        for (int kk = 0; kk < BK; ++kk){
            float ra[TM], rb[TN];
            #pragma unroll
            for (int i = 0; i < TM; i += 4)
                *(float4*)&ra[i] = *(const float4*)&As[kk][ty * TM + i];
            #pragma unroll
            for (int j = 0; j < TN; j += 4)
                *(float4*)&rb[j] = *(const float4*)&Bs[kk][tx * TN + j];
            #pragma unroll
            for (int i = 0; i < TM; i++)
                #pragma unroll
                for (int j = 0; j < TN; j++)
                    acc[i][j] = fmaf(ra[i], rb[j], acc[i][j]);
        }
        __syncthreads();
    }

    #pragma unroll
    for (int i = 0; i < TM; i++){
        int m = m0 + ty * TM + i;
        #pragma unroll
        for (int j = 0; j < TN; j++){
            int n = n0 + tx * TN + j;
            if (n < N){
                float v = acc[i][j] + bias[n];
                if (EPI == 1) v = gelu_f(v);
                if (EPI == 2) v += res[(size_t)m * N + n];
                C[(size_t)m * N + n] = v;
            }
        }
    }
}

// ---------------- fused causal attention (flash-style, fp32) ----------------
// One block per (b*h, 64-row q tile). 256 threads as 16x16.
// smem: Qt (Q^T), Kt (K^T, later aliased as P[q][k]), Vs -> exactly 48 KB.
__global__ void attn_k(const float* __restrict__ Qg, const float* __restrict__ Kg,
                       const float* __restrict__ Vg, float* __restrict__ Og)
{
    __shared__ float Qt[64][64];   // Qt[d][q]
    __shared__ float Kt[64][64];   // Kt[d][k]; reused as P[q][k]
    __shared__ float Vs[64][64];   // Vs[k][d]

    const int tid = threadIdx.x;
    const int tx  = tid & 15, ty = tid >> 4;
    const int bh  = blockIdx.y;
    const int b   = bh / NHEAD, h = bh % NHEAD;
    const int q0  = blockIdx.x * 64;
    const size_t base = (size_t)b * TSEQ * DMODEL + (size_t)h * DHEAD;

    // load Q tile transposed
    #pragma unroll
    for (int it = 0; it < 4; ++it){
        int e = (it * 256 + tid) * 4;
        int r = e >> 6, c = e & 63;
        float4 q4 = *(const float4*)(Qg + base + (size_t)(q0 + r) * DMODEL + c);
        Qt[c + 0][r] = q4.x; Qt[c + 1][r] = q4.y;
        Qt[c + 2][r] = q4.z; Qt[c + 3][r] = q4.w;
    }

    float m_i[4], l_i[4], o[4][4];
    #pragma unroll
    for (int i = 0; i < 4; i++){
        m_i[i] = -1e30f; l_i[i] = 0.f;
        #pragma unroll
        for (int j = 0; j < 4; j++) o[i][j] = 0.f;
    }

    const int nkt = blockIdx.x + 1;          // causal: only tiles with k0 <= q0
    for (int kt = 0; kt < nkt; ++kt){
        const int k0 = kt * 64;
        __syncthreads();                     // protect Kt/Vs (and Qt on first iter)
        #pragma unroll
        for (int it = 0; it < 4; ++it){
            int e = (it * 256 + tid) * 4;
            int r = e >> 6, c = e & 63;
            float4 k4 = *(const float4*)(Kg + base + (size_t)(k0 + r) * DMODEL + c);
            Kt[c + 0][r] = k4.x; Kt[c + 1][r] = k4.y;
            Kt[c + 2][r] = k4.z; Kt[c + 3][r] = k4.w;
            *(float4*)&Vs[r][c] = *(const float4*)(Vg + base + (size_t)(k0 + r) * DMODEL + c);
        }
        __syncthreads();

        // S = Q K^T
        float s[4][4];
        #pragma unroll
        for (int i = 0; i < 4; i++)
            #pragma unroll
            for (int j = 0; j < 4; j++) s[i][j] = 0.f;
        #pragma unroll 16
        for (int d = 0; d < 64; ++d){
            float qa[4], kb[4];
            *(float4*)qa = *(const float4*)&Qt[d][ty * 4];
            *(float4*)kb = *(const float4*)&Kt[d][tx * 4];
            #pragma unroll
            for (int i = 0; i < 4; i++)
                #pragma unroll
                for (int j = 0; j < 4; j++)
                    s[i][j] = fmaf(qa[i], kb[j], s[i][j]);
        }

        // scale + causal mask
        #pragma unroll
        for (int i = 0; i < 4; i++){
            int qg = q0 + ty * 4 + i;
            #pragma unroll
            for (int j = 0; j < 4; j++){
                int kg = k0 + tx * 4 + j;
                s[i][j] = (kg <= qg) ? s[i][j] * 0.125f : -1e30f;
            }
        }

        // online softmax (row reductions over the 16 tx lanes)
        float corr[4];
        #pragma unroll
        for (int i = 0; i < 4; i++){
            float mloc = fmaxf(fmaxf(s[i][0], s[i][1]), fmaxf(s[i][2], s[i][3]));
            #pragma unroll
            for (int off = 8; off; off >>= 1)
                mloc = fmaxf(mloc, __shfl_xor_sync(0xffffffffu, mloc, off, 16));
            float mn = fmaxf(m_i[i], mloc);
            corr[i] = expf(m_i[i] - mn);
            m_i[i]  = mn;
            float rs = 0.f;
            #pragma unroll
            for (int j = 0; j < 4; j++){
                float p = expf(s[i][j] - mn);   // masked -> exp(-huge) = 0
                s[i][j] = p;
                rs += p;
            }
            #pragma unroll
            for (int off = 8; off; off >>= 1)
                rs += __shfl_xor_sync(0xffffffffu, rs, off, 16);
            l_i[i] = l_i[i] * corr[i] + rs;
            #pragma unroll
            for (int j = 0; j < 4; j++) o[i][j] *= corr[i];
        }

        __syncthreads();                     // everyone done reading Kt as K^T
        #pragma unroll
        for (int i = 0; i < 4; i++)
            #pragma unroll
            for (int j = 0; j < 4; j++)
                Kt[ty * 4 + i][tx * 4 + j] = s[i][j];   // P[q][k]
        __syncthreads();

        // O += P V
        #pragma unroll 16
        for (int k = 0; k < 64; ++k){
            float vb[4];
            *(float4*)vb = *(const float4*)&Vs[k][tx * 4];
            #pragma unroll
            for (int i = 0; i < 4; i++){
                float p = Kt[ty * 4 + i][k];
                #pragma unroll
                for (int j = 0; j < 4; j++)
                    o[i][j] = fmaf(p, vb[j], o[i][j]);
            }
        }
    }

    // normalize + store
    #pragma unroll
    for (int i = 0; i < 4; i++){
        float inv = 1.f / l_i[i];
        int qg = q0 + ty * 4 + i;
        float4 r4 = make_float4(o[i][0]*inv, o[i][1]*inv, o[i][2]*inv, o[i][3]*inv);
        *(float4*)(Og + base + (size_t)qg * DMODEL + tx * 4) = r4;
    }
}

// ---------------- host orchestration ----------------
extern "C" void kernel_launch(void* const* d_in, const int* in_sizes, int n_in,
                              void* d_out, int out_size)
{
    const int*   ids = (const int*)  d_in[0];
    const float* emb = (const float*)d_in[1];
    const float* pos = (const float*)d_in[2];
    const float* Wq  = (const float*)d_in[3],  *bq = (const float*)d_in[4];
    const float* Wk  = (const float*)d_in[5],  *bk = (const float*)d_in[6];
    const float* Wv  = (const float*)d_in[7],  *bv = (const float*)d_in[8];
    const float* Wo  = (const float*)d_in[9],  *bo = (const float*)d_in[10];
    const float* l1g = (const float*)d_in[11], *l1b = (const float*)d_in[12];
    const float* l2g = (const float*)d_in[13], *l2b = (const float*)d_in[14];
    const float* W1  = (const float*)d_in[15], *b1 = (const float*)d_in[16];
    const float* W2  = (const float*)d_in[17], *b2 = (const float*)d_in[18];
    const float* lfg = (const float*)d_in[19], *lfb = (const float*)d_in[20];
    const float* Wu  = (const float*)d_in[21], *bu = (const float*)d_in[22];
    float* out = (float*)d_out;

    float *x, *h, *q, *k, *v, *z, *mm;
    cudaGetSymbolAddress((void**)&x,  g_x);
    cudaGetSymbolAddress((void**)&h,  g_h);
    cudaGetSymbolAddress((void**)&q,  g_q);
    cudaGetSymbolAddress((void**)&k,  g_k);
    cudaGetSymbolAddress((void**)&v,  g_v);
    cudaGetSymbolAddress((void**)&z,  g_z);
    cudaGetSymbolAddress((void**)&mm, g_m);

    const int M = MROWS, D = DMODEL, DM = DMLP, Vn = VOCAB;
    dim3 g64(D / 64, M / 64);                       // (12, 32)

    embed_k<<<M, 256>>>(ids, emb, pos, x);

    for (int l = 0; l < NLAYER; ++l){
        const size_t oD2 = (size_t)l * D * D;
        ln_k<<<M, 256>>>(x, l1g + l * D, l1b + l * D, h);
        gemm_k<64,64,16,4,4,0><<<g64, 256>>>(h, Wq + oD2, bq + l * D, nullptr, q, M, D, D);
        gemm_k<64,64,16,4,4,0><<<g64, 256>>>(h, Wk + oD2, bk + l * D, nullptr, k, M, D, D);
        gemm_k<64,64,16,4,4,0><<<g64, 256>>>(h, Wv + oD2, bv + l * D, nullptr, v, M, D, D);
        attn_k<<<dim3(TSEQ / 64, BATCH * NHEAD), 256>>>(q, k, v, z);
        gemm_k<64,64,16,4,4,2><<<g64, 256>>>(z, Wo + oD2, bo + l * D, x, x, M, D, D);
        ln_k<<<M, 256>>>(x, l2g + l * D, l2b + l * D, h);
        gemm_k<128,128,16,8,8,1><<<dim3(DM / 128, M / 128), 256>>>(
            h, W1 + (size_t)l * D * DM, b1 + l * DM, nullptr, mm, M, DM, D);
        gemm_k<64,64,16,4,4,2><<<g64, 256>>>(mm, W2 + (size_t)l * DM * D, b2 + l * D, x, x, M, D, DM);
    }

    ln_k<<<M, 256>>>(x, lfg, lfb, h);
    gemm_k<128,128,16,8,8,0><<<dim3((Vn + 127) / 128, M / 128), 256>>>(
        h, Wu, bu, nullptr, out, M, Vn, D);
}

// round 10
// speedup vs baseline: 1.0048x; 1.0029x over previous
#include <cuda_runtime.h>
#include <cuda_bf16.h>
#include <cstddef>

// ---------------- problem constants ----------------
#define BATCH 2
#define TSEQ  1024
#define MROWS (BATCH*TSEQ)      // 2048
#define DMODEL 768
#define NHEAD 12
#define DHEAD 64
#define DMLP  3072
#define NLAYER 12
#define VOCAB 50257

// ---------------- scratch (static device globals; no allocation) ----------------
__device__ float g_x [MROWS*DMODEL];   // residual stream
__device__ float g_h [MROWS*DMODEL];   // LN output
__device__ float g_q [MROWS*DMODEL];
__device__ float g_k [MROWS*DMODEL];
__device__ float g_v [MROWS*DMODEL];
__device__ float g_z [MROWS*DMODEL];   // attention output (pre-proj)
__device__ float g_m [MROWS*DMLP];     // MLP hidden

// ---------------- helpers ----------------
__device__ __forceinline__ float gelu_f(float x){
    // exact GELU: 0.5*x*(1+erf(x/sqrt(2))) — matches jax.nn.gelu(approximate=False)
    return 0.5f * x * (1.0f + erff(x * 0.70710678118654752440f));
}

// ---------------- embedding: x = emb[ids] + pos ----------------
__global__ void embed_k(const int* __restrict__ ids,
                        const float* __restrict__ emb,
                        const float* __restrict__ pos,
                        float* __restrict__ x)
{
    int row = blockIdx.x;                 // b*T + t
    int t   = row % TSEQ;
    int id  = ids[row];
    const float* er = emb + (size_t)id * DMODEL;
    const float* pr = pos + (size_t)t  * DMODEL;
    float* xr = x + (size_t)row * DMODEL;
    int tid = threadIdx.x;                // 256 threads, 3 elems each
    xr[tid]       = er[tid]       + pr[tid];
    xr[tid + 256] = er[tid + 256] + pr[tid + 256];
    xr[tid + 512] = er[tid + 512] + pr[tid + 512];
}

// ---------------- layernorm: one block (256 thr) per row, D=768 ----------------
__global__ void ln_k(const float* __restrict__ x,
                     const float* __restrict__ g,
                     const float* __restrict__ b,
                     float* __restrict__ out)
{
    __shared__ float red0[8], red1[8];
    int row = blockIdx.x, tid = threadIdx.x;
    const float* xr = x + (size_t)row * DMODEL;
    float v0 = xr[tid], v1 = xr[tid + 256], v2 = xr[tid + 512];
    float s  = v0 + v1 + v2;
    float s2 = v0*v0 + v1*v1 + v2*v2;
    #pragma unroll
    for (int off = 16; off; off >>= 1){
        s  += __shfl_xor_sync(0xffffffffu, s,  off);
        s2 += __shfl_xor_sync(0xffffffffu, s2, off);
    }
    int w = tid >> 5;
    if ((tid & 31) == 0){ red0[w] = s; red1[w] = s2; }
    __syncthreads();
    if (tid < 32){
        s  = (tid < 8) ? red0[tid] : 0.f;
        s2 = (tid < 8) ? red1[tid] : 0.f;
        #pragma unroll
        for (int off = 4; off; off >>= 1){
            s  += __shfl_xor_sync(0xffffffffu, s,  off);
            s2 += __shfl_xor_sync(0xffffffffu, s2, off);
        }
        if (tid == 0){ red0[0] = s; red1[0] = s2; }
    }
    __syncthreads();
    float mean = red0[0] * (1.f/768.f);
    float var  = red1[0] * (1.f/768.f) - mean * mean;
    float r    = rsqrtf(var + 1e-5f);
    float* orow = out + (size_t)row * DMODEL;
    orow[tid]       = (v0 - mean) * r * g[tid]       + b[tid];
    orow[tid + 256] = (v1 - mean) * r * g[tid + 256] + b[tid + 256];
    orow[tid + 512] = (v2 - mean) * r * g[tid + 512] + b[tid + 512];
}

// ---------------- tiled fp32 GEMM:  C = epi(A[M,K] * B[K,N] + bias) ----------------
// EPI: 0 = none, 1 = GELU, 2 = add residual (res[M,N])
template<int BM, int BN, int BK, int TM, int TN, int EPI>
__global__ void gemm_k(const float* __restrict__ A, const float* __restrict__ B,
                       const float* __restrict__ bias, const float* res,
                       float* C, int M, int N, int K)
{
    __shared__ float As[BK][BM];
    __shared__ float Bs[BK][BN];
    constexpr int NT = 256;
    const int tid = threadIdx.x;
    const int tx  = tid % (BN / TN);
    const int ty  = tid / (BN / TN);
    const int m0  = blockIdx.y * BM;
    const int n0  = blockIdx.x * BN;

    float acc[TM][TN];
    #pragma unroll
    for (int i = 0; i < TM; i++)
        #pragma unroll
        for (int j = 0; j < TN; j++) acc[i][j] = 0.f;

    const bool nvec = ((N & 3) == 0);

    for (int k0 = 0; k0 < K; k0 += BK){
        // load A tile (transposed into As[k][m]); M, K multiples of tile dims
        #pragma unroll
        for (int it = 0; it < (BM * BK) / (NT * 4); ++it){
            int e = (it * NT + tid) * 4;
            int r = e / BK, c = e % BK;
            float4 a4 = *(const float4*)(A + (size_t)(m0 + r) * K + k0 + c);
            As[c + 0][r] = a4.x; As[c + 1][r] = a4.y;
            As[c + 2][r] = a4.z; As[c + 3][r] = a4.w;
        }
        // load B tile (N may be ragged / unaligned, e.g. vocab=50257)
        #pragma unroll
        for (int it = 0; it < (BK * BN) / (NT * 4); ++it){
            int e = (it * NT + tid) * 4;
            int r = e / BN, c = e % BN;
            int gn = n0 + c;
            float4 b4;
            if (nvec && gn + 3 < N){
                b4 = *(const float4*)(B + (size_t)(k0 + r) * N + gn);
            } else {
                const float* bp = B + (size_t)(k0 + r) * N;
                b4.x = (gn + 0 < N) ? bp[gn + 0] : 0.f;
                b4.y = (gn + 1 < N) ? bp[gn + 1] : 0.f;
                b4.z = (gn + 2 < N) ? bp[gn + 2] : 0.f;
                b4.w = (gn + 3 < N) ? bp[gn + 3] : 0.f;
            }
            *(float4*)&Bs[r][c] = b4;
        }
        __syncthreads();
        #pragma unroll
        for (int kk = 0; kk < BK; ++kk){
            float ra[TM], rb[TN];
            #pragma unroll
            for (int i = 0; i < TM; i += 4)
                *(float4*)&ra[i] = *(const float4*)&As[kk][ty * TM + i];
            #pragma unroll
            for (int j = 0; j < TN; j += 4)
                *(float4*)&rb[j] = *(const float4*)&Bs[kk][tx * TN + j];
            #pragma unroll
            for (int i = 0; i < TM; i++)
                #pragma unroll
                for (int j = 0; j < TN; j++)
                    acc[i][j] = fmaf(ra[i], rb[j], acc[i][j]);
        }
        __syncthreads();
    }

    #pragma unroll
    for (int i = 0; i < TM; i++){
        int m = m0 + ty * TM + i;
        #pragma unroll
        for (int j = 0; j < TN; j++){
            int n = n0 + tx * TN + j;
            if (n < N){
                float v = acc[i][j] + bias[n];
                if (EPI == 1) v = gelu_f(v);
                if (EPI == 2) v += res[(size_t)m * N + n];
                C[(size_t)m * N + n] = v;
            }
        }
    }
}

// ---------------- fused causal attention (flash-style, fp32) ----------------
// One block per (b*h, 64-row q tile). 256 threads as 16x16.
// smem: Qt (Q^T), Kt (K^T, later aliased as P[q][k]), Vs -> exactly 48 KB.
__global__ void attn_k(const float* __restrict__ Qg, const float* __restrict__ Kg,
                       const float* __restrict__ Vg, float* __restrict__ Og)
{
    __shared__ float Qt[64][64];   // Qt[d][q]
    __shared__ float Kt[64][64];   // Kt[d][k]; reused as P[q][k]
    __shared__ float Vs[64][64];   // Vs[k][d]

    const int tid = threadIdx.x;
    const int tx  = tid & 15, ty = tid >> 4;
    const int bh  = blockIdx.y;
    const int b   = bh / NHEAD, h = bh % NHEAD;
    const int q0  = blockIdx.x * 64;
    const size_t base = (size_t)b * TSEQ * DMODEL + (size_t)h * DHEAD;

    // load Q tile transposed
    #pragma unroll
    for (int it = 0; it < 4; ++it){
        int e = (it * 256 + tid) * 4;
        int r = e >> 6, c = e & 63;
        float4 q4 = *(const float4*)(Qg + base + (size_t)(q0 + r) * DMODEL + c);
        Qt[c + 0][r] = q4.x; Qt[c + 1][r] = q4.y;
        Qt[c + 2][r] = q4.z; Qt[c + 3][r] = q4.w;
    }

    float m_i[4], l_i[4], o[4][4];
    #pragma unroll
    for (int i = 0; i < 4; i++){
        m_i[i] = -1e30f; l_i[i] = 0.f;
        #pragma unroll
        for (int j = 0; j < 4; j++) o[i][j] = 0.f;
    }

    const int nkt = blockIdx.x + 1;          // causal: only tiles with k0 <= q0
    for (int kt = 0; kt < nkt; ++kt){
        const int k0 = kt * 64;
        __syncthreads();                     // protect Kt/Vs (and Qt on first iter)
        #pragma unroll
        for (int it = 0; it < 4; ++it){
            int e = (it * 256 + tid) * 4;
            int r = e >> 6, c = e & 63;
            float4 k4 = *(const float4*)(Kg + base + (size_t)(k0 + r) * DMODEL + c);
            Kt[c + 0][r] = k4.x; Kt[c + 1][r] = k4.y;
            Kt[c + 2][r] = k4.z; Kt[c + 3][r] = k4.w;
            *(float4*)&Vs[r][c] = *(const float4*)(Vg + base + (size_t)(k0 + r) * DMODEL + c);
        }
        __syncthreads();

        // S = Q K^T
        float s[4][4];
        #pragma unroll
        for (int i = 0; i < 4; i++)
            #pragma unroll
            for (int j = 0; j < 4; j++) s[i][j] = 0.f;
        #pragma unroll 16
        for (int d = 0; d < 64; ++d){
            float qa[4], kb[4];
            *(float4*)qa = *(const float4*)&Qt[d][ty * 4];
            *(float4*)kb = *(const float4*)&Kt[d][tx * 4];
            #pragma unroll
            for (int i = 0; i < 4; i++)
                #pragma unroll
                for (int j = 0; j < 4; j++)
                    s[i][j] = fmaf(qa[i], kb[j], s[i][j]);
        }

        // scale + causal mask
        #pragma unroll
        for (int i = 0; i < 4; i++){
            int qg = q0 + ty * 4 + i;
            #pragma unroll
            for (int j = 0; j < 4; j++){
                int kg = k0 + tx * 4 + j;
                s[i][j] = (kg <= qg) ? s[i][j] * 0.125f : -1e30f;
            }
        }

        // online softmax (row reductions over the 16 tx lanes)
        float corr[4];
        #pragma unroll
        for (int i = 0; i < 4; i++){
            float mloc = fmaxf(fmaxf(s[i][0], s[i][1]), fmaxf(s[i][2], s[i][3]));
            #pragma unroll
            for (int off = 8; off; off >>= 1)
                mloc = fmaxf(mloc, __shfl_xor_sync(0xffffffffu, mloc, off, 16));
            float mn = fmaxf(m_i[i], mloc);
            corr[i] = expf(m_i[i] - mn);
            m_i[i]  = mn;
            float rs = 0.f;
            #pragma unroll
            for (int j = 0; j < 4; j++){
                float p = expf(s[i][j] - mn);   // masked -> exp(-huge) = 0
                s[i][j] = p;
                rs += p;
            }
            #pragma unroll
            for (int off = 8; off; off >>= 1)
                rs += __shfl_xor_sync(0xffffffffu, rs, off, 16);
            l_i[i] = l_i[i] * corr[i] + rs;
            #pragma unroll
            for (int j = 0; j < 4; j++) o[i][j] *= corr[i];
        }

        __syncthreads();                     // everyone done reading Kt as K^T
        #pragma unroll
        for (int i = 0; i < 4; i++)
            #pragma unroll
            for (int j = 0; j < 4; j++)
                Kt[ty * 4 + i][tx * 4 + j] = s[i][j];   // P[q][k]
        __syncthreads();

        // O += P V
        #pragma unroll 16
        for (int k = 0; k < 64; ++k){
            float vb[4];
            *(float4*)vb = *(const float4*)&Vs[k][tx * 4];
            #pragma unroll
            for (int i = 0; i < 4; i++){
                float p = Kt[ty * 4 + i][k];
                #pragma unroll
                for (int j = 0; j < 4; j++)
                    o[i][j] = fmaf(p, vb[j], o[i][j]);
            }
        }
    }

    // normalize + store
    #pragma unroll
    for (int i = 0; i < 4; i++){
        float inv = 1.f / l_i[i];
        int qg = q0 + ty * 4 + i;
        float4 r4 = make_float4(o[i][0]*inv, o[i][1]*inv, o[i][2]*inv, o[i][3]*inv);
        *(float4*)(Og + base + (size_t)qg * DMODEL + tx * 4) = r4;
    }
}

// ---------------- host orchestration ----------------
extern "C" void kernel_launch(void* const* d_in, const int* in_sizes, int n_in,
                              void* d_out, int out_size)
{
    const int*   ids = (const int*)  d_in[0];
    const float* emb = (const float*)d_in[1];
    const float* pos = (const float*)d_in[2];
    const float* Wq  = (const float*)d_in[3],  *bq = (const float*)d_in[4];
    const float* Wk  = (const float*)d_in[5],  *bk = (const float*)d_in[6];
    const float* Wv  = (const float*)d_in[7],  *bv = (const float*)d_in[8];
    const float* Wo  = (const float*)d_in[9],  *bo = (const float*)d_in[10];
    const float* l1g = (const float*)d_in[11], *l1b = (const float*)d_in[12];
    const float* l2g = (const float*)d_in[13], *l2b = (const float*)d_in[14];
    const float* W1  = (const float*)d_in[15], *b1 = (const float*)d_in[16];
    const float* W2  = (const float*)d_in[17], *b2 = (const float*)d_in[18];
    const float* lfg = (const float*)d_in[19], *lfb = (const float*)d_in[20];
    const float* Wu  = (const float*)d_in[21], *bu = (const float*)d_in[22];
    float* out = (float*)d_out;

    float *x, *h, *q, *k, *v, *z, *mm;
    cudaGetSymbolAddress((void**)&x,  g_x);
    cudaGetSymbolAddress((void**)&h,  g_h);
    cudaGetSymbolAddress((void**)&q,  g_q);
    cudaGetSymbolAddress((void**)&k,  g_k);
    cudaGetSymbolAddress((void**)&v,  g_v);
    cudaGetSymbolAddress((void**)&z,  g_z);
    cudaGetSymbolAddress((void**)&mm, g_m);

    const int M = MROWS, D = DMODEL, DM = DMLP, Vn = VOCAB;
    dim3 g64(D / 64, M / 64);                       // (12, 32)

    embed_k<<<M, 256>>>(ids, emb, pos, x);

    for (int l = 0; l < NLAYER; ++l){
        const size_t oD2 = (size_t)l * D * D;
        ln_k<<<M, 256>>>(x, l1g + l * D, l1b + l * D, h);
        gemm_k<64,64,16,4,4,0><<<g64, 256>>>(h, Wq + oD2, bq + l * D, nullptr, q, M, D, D);
        gemm_k<64,64,16,4,4,0><<<g64, 256>>>(h, Wk + oD2, bk + l * D, nullptr, k, M, D, D);
        gemm_k<64,64,16,4,4,0><<<g64, 256>>>(h, Wv + oD2, bv + l * D, nullptr, v, M, D, D);
        attn_k<<<dim3(TSEQ / 64, BATCH * NHEAD), 256>>>(q, k, v, z);
        gemm_k<64,64,16,4,4,2><<<g64, 256>>>(z, Wo + oD2, bo + l * D, x, x, M, D, D);
        ln_k<<<M, 256>>>(x, l2g + l * D, l2b + l * D, h);
        gemm_k<128,128,16,8,8,1><<<dim3(DM / 128, M / 128), 256>>>(
            h, W1 + (size_t)l * D * DM, b1 + l * DM, nullptr, mm, M, DM, D);
        gemm_k<64,64,16,4,4,2><<<g64, 256>>>(mm, W2 + (size_t)l * DM * D, b2 + l * D, x, x, M, D, DM);
    }

    ln_k<<<M, 256>>>(x, lfg, lfb, h);
    gemm_k<128,128,16,8,8,0><<<dim3((Vn + 127) / 128, M / 128), 256>>>(
        h, Wu, bu, nullptr, out, M, Vn, D);
}

// round 13
// speedup vs baseline: 2.7261x; 2.7131x over previous
#include <cuda_runtime.h>
#include <cuda_bf16.h>
#include <cstdint>
#include <cstddef>

// ---------------- problem constants ----------------
#define BATCH 2
#define TSEQ  1024
#define MROWS (BATCH*TSEQ)      // 2048
#define DMODEL 768
#define NHEAD 12
#define DHEAD 64
#define DMLP  3072
#define NLAYER 12
#define VOCAB 50257
#define DQKV  (3*DMODEL)        // 2304

// ---------------- scratch (static device globals; no allocation) ----------------
__device__ float g_x  [MROWS*DMODEL];          // residual stream (fp32)
__device__ float g_qkv[MROWS*DQKV];            // fused qkv output (fp32)
__device__ __nv_bfloat16 g_hh[MROWS*DMODEL], g_hl[MROWS*DMODEL];   // LN out split
__device__ __nv_bfloat16 g_zh[MROWS*DMODEL], g_zl[MROWS*DMODEL];   // attn out split
__device__ __nv_bfloat16 g_mh[MROWS*DMLP],   g_ml[MROWS*DMLP];     // MLP hidden split

// split+transposed weights, [N][K] K-major bf16 planes
__device__ __nv_bfloat16 g_wqkv_h[NLAYER*DQKV*DMODEL],  g_wqkv_l[NLAYER*DQKV*DMODEL];
__device__ __nv_bfloat16 g_wo_h  [NLAYER*DMODEL*DMODEL],g_wo_l  [NLAYER*DMODEL*DMODEL];
__device__ __nv_bfloat16 g_w1_h  [NLAYER*DMLP*DMODEL],  g_w1_l  [NLAYER*DMLP*DMODEL];
__device__ __nv_bfloat16 g_w2_h  [NLAYER*DMODEL*DMLP],  g_w2_l  [NLAYER*DMODEL*DMLP];
__device__ __nv_bfloat16 g_wu_h  [VOCAB*DMODEL],        g_wu_l  [VOCAB*DMODEL];
__device__ float g_bqkv[NLAYER*DQKV];

// ---------------- PTX helpers (plain sm_80+ features only) ----------------
__device__ __forceinline__ uint32_t smem_u32(const void* p){
    uint32_t a;
    asm("{ .reg .u64 t; cvta.to.shared.u64 t, %1; cvt.u32.u64 %0, t; }" : "=r"(a) : "l"(p));
    return a;
}
__device__ __forceinline__ void cpa16(uint32_t dst, const void* src, uint32_t srcsize){
    asm volatile("cp.async.cg.shared.global [%0], [%1], 16, %2;"
                 :: "r"(dst), "l"(src), "r"(srcsize) : "memory");
}
__device__ __forceinline__ void cpa_commit(){
    asm volatile("cp.async.commit_group;" ::: "memory");
}
__device__ __forceinline__ void cpa_wait1(){
    asm volatile("cp.async.wait_group 1;" ::: "memory");
}
__device__ __forceinline__ void cpa_wait0(){
    asm volatile("cp.async.wait_group 0;" ::: "memory");
}
__device__ __forceinline__ void ldsm4(uint32_t* r, uint32_t addr){
    asm volatile("ldmatrix.sync.aligned.m8n8.x4.shared.b16 {%0,%1,%2,%3}, [%4];"
                 : "=r"(r[0]), "=r"(r[1]), "=r"(r[2]), "=r"(r[3]) : "r"(addr));
}
__device__ __forceinline__ void mma_bf16(float* c, const uint32_t* a, const uint32_t* b){
    asm volatile("mma.sync.aligned.m16n8k16.row.col.f32.bf16.bf16.f32 "
                 "{%0,%1,%2,%3}, {%4,%5,%6,%7}, {%8,%9}, {%0,%1,%2,%3};"
                 : "+f"(c[0]), "+f"(c[1]), "+f"(c[2]), "+f"(c[3])
                 : "r"(a[0]), "r"(a[1]), "r"(a[2]), "r"(a[3]), "r"(b[0]), "r"(b[1]));
}
#define SMEM_SWIZZLE_128B(o) ((o) ^ (((o) >> 3) & 0x70))

// ---------------- small helpers ----------------
__device__ __forceinline__ float gelu_f(float x){
    return 0.5f * x * (1.0f + erff(x * 0.70710678118654752440f));
}
__device__ __forceinline__ void split2(float v, __nv_bfloat16& h, __nv_bfloat16& l){
    h = __float2bfloat16(v);
    l = __float2bfloat16(v - __bfloat162float(h));
}

// ---------------- weight split+transpose:  src[K][N] -> dst planes [N][K] ----------------
__global__ void tsplit_k(const float* __restrict__ src, size_t srcLS,
                         __nv_bfloat16* __restrict__ dh, __nv_bfloat16* __restrict__ dl,
                         size_t dstLS, int dstRowOff, int ldDst, int K, int N)
{
    __shared__ float t[32][33];
    int l  = blockIdx.z;
    int k0 = blockIdx.y * 32, n0 = blockIdx.x * 32;
    int tx = threadIdx.x & 31, ty = threadIdx.x >> 5;   // 256 thr: ty 0..7
    const float* s = src + (size_t)l * srcLS;
    #pragma unroll
    for (int i = ty; i < 32; i += 8){
        int k = k0 + i, n = n0 + tx;
        t[i][tx] = (k < K && n < N) ? s[(size_t)k * N + n] : 0.f;
    }
    __syncthreads();
    __nv_bfloat16* ph = dh + (size_t)l * dstLS;
    __nv_bfloat16* pl = dl + (size_t)l * dstLS;
    #pragma unroll
    for (int i = ty; i < 32; i += 8){
        int n = n0 + i, k = k0 + tx;
        if (n < N && k < K){
            float v = t[tx][i];
            __nv_bfloat16 h, lo; split2(v, h, lo);
            size_t off = (size_t)(dstRowOff + n) * ldDst + k;
            ph[off] = h; pl[off] = lo;
        }
    }
}

__global__ void bcat_k(const float* __restrict__ bq, const float* __restrict__ bk,
                       const float* __restrict__ bv, float* __restrict__ dst)
{
    int l = blockIdx.y;
    int i = blockIdx.x * 256 + threadIdx.x;
    if (i < DQKV){
        float v = (i < 768) ? bq[l*768 + i] : (i < 1536) ? bk[l*768 + i - 768]
                                                         : bv[l*768 + i - 1536];
        dst[l*DQKV + i] = v;
    }
}

// ---------------- embedding ----------------
__global__ void embed_k(const int* __restrict__ ids, const float* __restrict__ emb,
                        const float* __restrict__ pos, float* __restrict__ x)
{
    int row = blockIdx.x, t = row % TSEQ, id = ids[row];
    const float* er = emb + (size_t)id * DMODEL;
    const float* pr = pos + (size_t)t  * DMODEL;
    float* xr = x + (size_t)row * DMODEL;
    int tid = threadIdx.x;
    xr[tid]       = er[tid]       + pr[tid];
    xr[tid + 256] = er[tid + 256] + pr[tid + 256];
    xr[tid + 512] = er[tid + 512] + pr[tid + 512];
}

// ---------------- layernorm -> bf16 hi/lo split ----------------
__global__ void ln_split_k(const float* __restrict__ x, const float* __restrict__ g,
                           const float* __restrict__ b,
                           __nv_bfloat16* __restrict__ oh, __nv_bfloat16* __restrict__ ol)
{
    __shared__ float red0[8], red1[8];
    int row = blockIdx.x, tid = threadIdx.x;
    const float* xr = x + (size_t)row * DMODEL;
    float v0 = xr[tid], v1 = xr[tid + 256], v2 = xr[tid + 512];
    float s  = v0 + v1 + v2;
    float s2 = v0*v0 + v1*v1 + v2*v2;
    #pragma unroll
    for (int off = 16; off; off >>= 1){
        s  += __shfl_xor_sync(0xffffffffu, s,  off);
        s2 += __shfl_xor_sync(0xffffffffu, s2, off);
    }
    int w = tid >> 5;
    if ((tid & 31) == 0){ red0[w] = s; red1[w] = s2; }
    __syncthreads();
    if (tid < 32){
        s  = (tid < 8) ? red0[tid] : 0.f;
        s2 = (tid < 8) ? red1[tid] : 0.f;
        #pragma unroll
        for (int off = 4; off; off >>= 1){
            s  += __shfl_xor_sync(0xffffffffu, s,  off);
            s2 += __shfl_xor_sync(0xffffffffu, s2, off);
        }
        if (tid == 0){ red0[0] = s; red1[0] = s2; }
    }
    __syncthreads();
    float mean = red0[0] * (1.f/768.f);
    float var  = red1[0] * (1.f/768.f) - mean * mean;
    float r    = rsqrtf(var + 1e-5f);
    size_t base = (size_t)row * DMODEL;
    #pragma unroll
    for (int e = 0; e < 3; ++e){
        int idx = tid + e*256;
        float vv = (e==0?v0:(e==1?v1:v2));
        float y = (vv - mean) * r * g[idx] + b[idx];
        __nv_bfloat16 h, lo; split2(y, h, lo);
        oh[base + idx] = h; ol[base + idx] = lo;
    }
}

// ---------------- mma.sync bf16-split GEMM ----------------
// C[M,N] = epi( (Ah+Al) * (Bh+Bl)^T + bias )   A:[M][K] planes, B:[N][K] planes.
// EPI: 0 = fp32 out ; 2 = fp32 out + residual ; 3 = GELU -> bf16 split out (Ch/Cl)
#define WS_THREADS 256
#define WS_NSTAGE 3
#define WS_STAGE_BYTES 65536          // 4 buffers (Ah,Al,Bh,Bl) x 16KB each
#define WS_SMEM (WS_NSTAGE*WS_STAGE_BYTES)

template<int EPI>
__global__ __launch_bounds__(WS_THREADS, 1)
void gemm_ws(const __nv_bfloat16* __restrict__ Ah, const __nv_bfloat16* __restrict__ Al,
             const __nv_bfloat16* __restrict__ Bh, const __nv_bfloat16* __restrict__ Bl,
             const float* __restrict__ bias, const float* __restrict__ res,
             float* __restrict__ C, __nv_bfloat16* __restrict__ Ch,
             __nv_bfloat16* __restrict__ Cl, int M, int N, int K)
{
    extern __shared__ char smem[];
    const uint32_t sb = smem_u32(smem);
    const int tid = threadIdx.x, wid = tid >> 5, lane = tid & 31;
    const int warp_m = wid & 1;        // 0..1 -> 64 rows each
    const int warp_n = wid >> 1;       // 0..3 -> 32 cols each
    const int m0 = blockIdx.y * 128, n0 = blockIdx.x * 128;

    float acc[16][4];
    #pragma unroll
    for (int i = 0; i < 16; i++)
        #pragma unroll
        for (int j = 0; j < 4; j++) acc[i][j] = 0.f;

    const int nch = K >> 6;   // K/64 stages of work

    // ---- stage loader: 16B cp.async chunks, SW128-swizzled rows of 128B ----
    auto load_stage = [&](int st, int k0){
        const uint32_t s0 = sb + (uint32_t)st * WS_STAGE_BYTES;
        #pragma unroll
        for (int it = 0; it < 4; ++it){
            int idx = it * 256 + tid;            // 0..1023
            int row = idx >> 3, ch = idx & 7;
            uint32_t off = SMEM_SWIZZLE_128B(row*128 + ch*16);
            const size_t aoff = (size_t)(m0 + row) * K + k0 + ch*8;
            cpa16(s0 +         off, Ah + aoff, 16);
            cpa16(s0 + 16384 + off, Al + aoff, 16);
            int brow = n0 + row;
            uint32_t sz = (brow < N) ? 16u : 0u;
            if (brow >= N) brow = N - 1;         // keep address valid
            const size_t boff = (size_t)brow * K + k0 + ch*8;
            cpa16(s0 + 32768 + off, Bh + boff, sz);
            cpa16(s0 + 49152 + off, Bl + boff, sz);
        }
        cpa_commit();
    };

    // ---- compute one 64-deep K stage ----
    auto compute_stage = [&](int st){
        const uint32_t sAh = sb + (uint32_t)st * WS_STAGE_BYTES;
        const uint32_t sAl = sAh + 16384;
        const uint32_t sBh = sAh + 32768;
        const uint32_t sBl = sAh + 49152;
        #pragma unroll
        for (int ks = 0; ks < 4; ++ks){
            uint32_t ah[4][4], al[4][4], bh[4][2], bl[4][2];
            // A fragments: 4 m-tiles of 16 rows
            const int arow = warp_m*64 + (lane & 7) + ((lane >> 3) & 1) * 8;
            const int akc  = ks*16 + ((lane >> 4) & 1) * 8;
            #pragma unroll
            for (int mt = 0; mt < 4; ++mt){
                uint32_t off = SMEM_SWIZZLE_128B((arow + mt*16)*128 + akc*2);
                ldsm4(ah[mt], sAh + off);
                ldsm4(al[mt], sAl + off);
            }
            // B fragments: 4 n-tiles of 8 cols (two x4 loads)
            const int brow0 = warp_n*32 + ((lane >> 4) & 1) * 8 + (lane & 7);
            const int bkc   = ks*16 + ((lane >> 3) & 1) * 8;
            #pragma unroll
            for (int nq = 0; nq < 2; ++nq){
                uint32_t off = SMEM_SWIZZLE_128B((brow0 + nq*16)*128 + bkc*2);
                uint32_t r[4];
                ldsm4(r, sBh + off);
                bh[2*nq][0] = r[0]; bh[2*nq][1] = r[1];
                bh[2*nq+1][0] = r[2]; bh[2*nq+1][1] = r[3];
                ldsm4(r, sBl + off);
                bl[2*nq][0] = r[0]; bl[2*nq][1] = r[1];
                bl[2*nq+1][0] = r[2]; bl[2*nq+1][1] = r[3];
            }
            // 3-pass split MMA: AhBh + AhBl + AlBh
            #pragma unroll
            for (int mt = 0; mt < 4; ++mt)
                #pragma unroll
                for (int nt = 0; nt < 4; ++nt){
                    float* c = acc[mt*4 + nt];
                    mma_bf16(c, ah[mt], bh[nt]);
                    mma_bf16(c, ah[mt], bl[nt]);
                    mma_bf16(c, al[mt], bh[nt]);
                }
        }
    };

    // ---- pipelined mainloop ----
    load_stage(0, 0);
    load_stage(1, 64);
    for (int c = 0; c < nch; ++c){
        if (c + 1 < nch) cpa_wait1(); else cpa_wait0();
        __syncthreads();
        int p = c + WS_NSTAGE - 1;
        if (p < nch) load_stage(p % WS_NSTAGE, p * 64);
        else cpa_commit();
        compute_stage(c % WS_NSTAGE);
    }

    // ---- epilogue ----
    const int lr = lane >> 2, lc = (lane & 3) * 2;
    const bool nvec = ((N & 1) == 0);
    #pragma unroll
    for (int mt = 0; mt < 4; ++mt){
        #pragma unroll
        for (int nt = 0; nt < 4; ++nt){
            const float* cfr = acc[mt*4 + nt];
            const int n = n0 + warp_n*32 + nt*8 + lc;
            #pragma unroll
            for (int half = 0; half < 2; ++half){
                const int m = m0 + warp_m*64 + mt*16 + lr + half*8;
                float v0 = cfr[half*2 + 0];
                float v1 = cfr[half*2 + 1];
                if (EPI == 3){
                    v0 = gelu_f(v0 + bias[n]);
                    v1 = gelu_f(v1 + bias[n+1]);
                    __nv_bfloat16 h0, l0, h1, l1;
                    split2(v0, h0, l0); split2(v1, h1, l1);
                    __nv_bfloat162 hp; hp.x = h0; hp.y = h1;
                    __nv_bfloat162 lp; lp.x = l0; lp.y = l1;
                    *(__nv_bfloat162*)(Ch + (size_t)m * N + n) = hp;
                    *(__nv_bfloat162*)(Cl + (size_t)m * N + n) = lp;
                } else {
                    if (n < N) v0 += bias[n];
                    if (n + 1 < N) v1 += bias[n+1];
                    if (EPI == 2){
                        const float2 r2 = *(const float2*)(res + (size_t)m * N + n);
                        v0 += r2.x; v1 += r2.y;
                    }
                    if (nvec && (n + 1 < N)){
                        float2 o2; o2.x = v0; o2.y = v1;
                        *(float2*)(C + (size_t)m * N + n) = o2;
                    } else {
                        if (n < N)     C[(size_t)m * N + n]     = v0;
                        if (n + 1 < N) C[(size_t)m * N + n + 1] = v1;
                    }
                }
            }
        }
    }
}

// ---------------- fused causal attention (flash-style, fp32 SIMT) ----------------
// reads fused qkv buffer [M][2304]; writes attn output as bf16 hi/lo planes [M][768]
__global__ void attn_k(const float* __restrict__ QKV,
                       __nv_bfloat16* __restrict__ Zh, __nv_bfloat16* __restrict__ Zl)
{
    __shared__ float Qt[64][64];
    __shared__ float Kt[64][64];   // reused as P[q][k]
    __shared__ float Vs[64][64];

    const int tid = threadIdx.x;
    const int tx  = tid & 15, ty = tid >> 4;
    const int bh  = blockIdx.y;
    const int b   = bh / NHEAD, h = bh % NHEAD;
    const int q0  = blockIdx.x * 64;
    const size_t rs = DQKV;
    const size_t base = (size_t)b * TSEQ * rs + (size_t)h * DHEAD;
    const float* Qg = QKV + base;
    const float* Kg = QKV + base + DMODEL;
    const float* Vg = QKV + base + 2*DMODEL;

    #pragma unroll
    for (int it = 0; it < 4; ++it){
        int e = (it * 256 + tid) * 4;
        int r = e >> 6, c = e & 63;
        float4 q4 = *(const float4*)(Qg + (size_t)(q0 + r) * rs + c);
        Qt[c + 0][r] = q4.x; Qt[c + 1][r] = q4.y;
        Qt[c + 2][r] = q4.z; Qt[c + 3][r] = q4.w;
    }

    float m_i[4], l_i[4], o[4][4];
    #pragma unroll
    for (int i = 0; i < 4; i++){
        m_i[i] = -1e30f; l_i[i] = 0.f;
        #pragma unroll
        for (int j = 0; j < 4; j++) o[i][j] = 0.f;
    }

    const int nkt = blockIdx.x + 1;
    for (int kt = 0; kt < nkt; ++kt){
        const int k0 = kt * 64;
        __syncthreads();
        #pragma unroll
        for (int it = 0; it < 4; ++it){
            int e = (it * 256 + tid) * 4;
            int r = e >> 6, c = e & 63;
            float4 k4 = *(const float4*)(Kg + (size_t)(k0 + r) * rs + c);
            Kt[c + 0][r] = k4.x; Kt[c + 1][r] = k4.y;
            Kt[c + 2][r] = k4.z; Kt[c + 3][r] = k4.w;
            *(float4*)&Vs[r][c] = *(const float4*)(Vg + (size_t)(k0 + r) * rs + c);
        }
        __syncthreads();

        float s[4][4];
        #pragma unroll
        for (int i = 0; i < 4; i++)
            #pragma unroll
            for (int j = 0; j < 4; j++) s[i][j] = 0.f;
        #pragma unroll 16
        for (int d = 0; d < 64; ++d){
            float qa[4], kb[4];
            *(float4*)qa = *(const float4*)&Qt[d][ty * 4];
            *(float4*)kb = *(const float4*)&Kt[d][tx * 4];
            #pragma unroll
            for (int i = 0; i < 4; i++)
                #pragma unroll
                for (int j = 0; j < 4; j++)
                    s[i][j] = fmaf(qa[i], kb[j], s[i][j]);
        }

        #pragma unroll
        for (int i = 0; i < 4; i++){
            int qg = q0 + ty * 4 + i;
            #pragma unroll
            for (int j = 0; j < 4; j++){
                int kg = k0 + tx * 4 + j;
                s[i][j] = (kg <= qg) ? s[i][j] * 0.125f : -1e30f;
            }
        }

        float corr[4];
        #pragma unroll
        for (int i = 0; i < 4; i++){
            float mloc = fmaxf(fmaxf(s[i][0], s[i][1]), fmaxf(s[i][2], s[i][3]));
            #pragma unroll
            for (int off = 8; off; off >>= 1)
                mloc = fmaxf(mloc, __shfl_xor_sync(0xffffffffu, mloc, off, 16));
            float mn = fmaxf(m_i[i], mloc);
            corr[i] = expf(m_i[i] - mn);
            m_i[i]  = mn;
            float rsum = 0.f;
            #pragma unroll
            for (int j = 0; j < 4; j++){
                float p = expf(s[i][j] - mn);
                s[i][j] = p; rsum += p;
            }
            #pragma unroll
            for (int off = 8; off; off >>= 1)
                rsum += __shfl_xor_sync(0xffffffffu, rsum, off, 16);
            l_i[i] = l_i[i] * corr[i] + rsum;
            #pragma unroll
            for (int j = 0; j < 4; j++) o[i][j] *= corr[i];
        }

        __syncthreads();
        #pragma unroll
        for (int i = 0; i < 4; i++)
            #pragma unroll
            for (int j = 0; j < 4; j++)
                Kt[ty * 4 + i][tx * 4 + j] = s[i][j];
        __syncthreads();

        #pragma unroll 16
        for (int k = 0; k < 64; ++k){
            float vb[4];
            *(float4*)vb = *(const float4*)&Vs[k][tx * 4];
            #pragma unroll
            for (int i = 0; i < 4; i++){
                float p = Kt[ty * 4 + i][k];
                #pragma unroll
                for (int j = 0; j < 4; j++)
                    o[i][j] = fmaf(p, vb[j], o[i][j]);
            }
        }
    }

    #pragma unroll
    for (int i = 0; i < 4; i++){
        float inv = 1.f / l_i[i];
        int qg = q0 + ty * 4 + i;
        size_t off = (size_t)(b * TSEQ + qg) * DMODEL + h * DHEAD + tx * 4;
        float o0 = o[i][0]*inv, o1 = o[i][1]*inv, o2 = o[i][2]*inv, o3 = o[i][3]*inv;
        __nv_bfloat16 h0,l0,h1,l1,h2,l2,h3,l3;
        split2(o0,h0,l0); split2(o1,h1,l1); split2(o2,h2,l2); split2(o3,h3,l3);
        __nv_bfloat162 hp0; hp0.x=h0; hp0.y=h1;
        __nv_bfloat162 hp1; hp1.x=h2; hp1.y=h3;
        __nv_bfloat162 lp0; lp0.x=l0; lp0.y=l1;
        __nv_bfloat162 lp1; lp1.x=l2; lp1.y=l3;
        *(__nv_bfloat162*)(Zh + off)     = hp0;
        *(__nv_bfloat162*)(Zh + off + 2) = hp1;
        *(__nv_bfloat162*)(Zl + off)     = lp0;
        *(__nv_bfloat162*)(Zl + off + 2) = lp1;
    }
}

// ---------------- host orchestration ----------------
extern "C" void kernel_launch(void* const* d_in, const int* in_sizes, int n_in,
                              void* d_out, int out_size)
{
    const int*   ids = (const int*)  d_in[0];
    const float* emb = (const float*)d_in[1];
    const float* pos = (const float*)d_in[2];
    const float* Wq  = (const float*)d_in[3],  *bq = (const float*)d_in[4];
    const float* Wk  = (const float*)d_in[5],  *bk = (const float*)d_in[6];
    const float* Wv  = (const float*)d_in[7],  *bv = (const float*)d_in[8];
    const float* Wo  = (const float*)d_in[9],  *bo = (const float*)d_in[10];
    const float* l1g = (const float*)d_in[11], *l1b = (const float*)d_in[12];
    const float* l2g = (const float*)d_in[13], *l2b = (const float*)d_in[14];
    const float* W1  = (const float*)d_in[15], *b1 = (const float*)d_in[16];
    const float* W2  = (const float*)d_in[17], *b2 = (const float*)d_in[18];
    const float* lfg = (const float*)d_in[19], *lfb = (const float*)d_in[20];
    const float* Wu  = (const float*)d_in[21], *bu = (const float*)d_in[22];
    float* out = (float*)d_out;

    float *x, *qkv, *bqkv;
    __nv_bfloat16 *hh, *hl, *zh, *zl, *mh, *ml;
    __nv_bfloat16 *wqh, *wql, *woh, *wol, *w1h, *w1l, *w2h, *w2l, *wuh, *wul;
    cudaGetSymbolAddress((void**)&x,    g_x);
    cudaGetSymbolAddress((void**)&qkv,  g_qkv);
    cudaGetSymbolAddress((void**)&bqkv, g_bqkv);
    cudaGetSymbolAddress((void**)&hh,   g_hh);  cudaGetSymbolAddress((void**)&hl, g_hl);
    cudaGetSymbolAddress((void**)&zh,   g_zh);  cudaGetSymbolAddress((void**)&zl, g_zl);
    cudaGetSymbolAddress((void**)&mh,   g_mh);  cudaGetSymbolAddress((void**)&ml, g_ml);
    cudaGetSymbolAddress((void**)&wqh,  g_wqkv_h); cudaGetSymbolAddress((void**)&wql, g_wqkv_l);
    cudaGetSymbolAddress((void**)&woh,  g_wo_h);   cudaGetSymbolAddress((void**)&wol, g_wo_l);
    cudaGetSymbolAddress((void**)&w1h,  g_w1_h);   cudaGetSymbolAddress((void**)&w1l, g_w1_l);
    cudaGetSymbolAddress((void**)&w2h,  g_w2_h);   cudaGetSymbolAddress((void**)&w2l, g_w2_l);
    cudaGetSymbolAddress((void**)&wuh,  g_wu_h);   cudaGetSymbolAddress((void**)&wul, g_wu_l);

    cudaFuncSetAttribute(gemm_ws<0>, cudaFuncAttributeMaxDynamicSharedMemorySize, WS_SMEM);
    cudaFuncSetAttribute(gemm_ws<2>, cudaFuncAttributeMaxDynamicSharedMemorySize, WS_SMEM);
    cudaFuncSetAttribute(gemm_ws<3>, cudaFuncAttributeMaxDynamicSharedMemorySize, WS_SMEM);

    const int M = MROWS, D = DMODEL, DM = DMLP, Vn = VOCAB;

    // ---- weight split + transpose (to [N][K] bf16 planes) ----
    const size_t d2 = (size_t)D * D, dm2 = (size_t)D * DM;
    tsplit_k<<<dim3(24, 24, NLAYER), 256>>>(Wq, d2, wqh, wql, (size_t)DQKV*D, 0,    D,  D, D);
    tsplit_k<<<dim3(24, 24, NLAYER), 256>>>(Wk, d2, wqh, wql, (size_t)DQKV*D, 768,  D,  D, D);
    tsplit_k<<<dim3(24, 24, NLAYER), 256>>>(Wv, d2, wqh, wql, (size_t)DQKV*D, 1536, D,  D, D);
    tsplit_k<<<dim3(24, 24, NLAYER), 256>>>(Wo, d2, woh, wol, d2,             0,    D,  D, D);
    tsplit_k<<<dim3(96, 24, NLAYER), 256>>>(W1, dm2, w1h, w1l, dm2,           0,    D,  D, DM);
    tsplit_k<<<dim3(24, 96, NLAYER), 256>>>(W2, dm2, w2h, w2l, dm2,           0,    DM, DM, D);
    tsplit_k<<<dim3((Vn + 31)/32, 24, 1), 256>>>(Wu, 0, wuh, wul, 0,          0,    D,  D, Vn);
    bcat_k<<<dim3((DQKV + 255)/256, NLAYER), 256>>>(bq, bk, bv, bqkv);

    embed_k<<<M, 256>>>(ids, emb, pos, x);

    const dim3 gQKV(DQKV/128, M/128);      // (18,16)
    const dim3 gD  (D/128,    M/128);      // (6,16)
    const dim3 gM1 (DM/128,   M/128);      // (24,16)
    const dim3 gLM ((Vn + 127)/128, M/128);

    for (int l = 0; l < NLAYER; ++l){
        ln_split_k<<<M, 256>>>(x, l1g + l*D, l1b + l*D, hh, hl);
        gemm_ws<0><<<gQKV, WS_THREADS, WS_SMEM>>>(hh, hl,
            wqh + (size_t)l*DQKV*D, wql + (size_t)l*DQKV*D,
            bqkv + l*DQKV, nullptr, qkv, nullptr, nullptr, M, DQKV, D);
        attn_k<<<dim3(TSEQ/64, BATCH*NHEAD), 256>>>(qkv, zh, zl);
        gemm_ws<2><<<gD, WS_THREADS, WS_SMEM>>>(zh, zl,
            woh + (size_t)l*d2, wol + (size_t)l*d2,
            bo + l*D, x, x, nullptr, nullptr, M, D, D);
        ln_split_k<<<M, 256>>>(x, l2g + l*D, l2b + l*D, hh, hl);
        gemm_ws<3><<<gM1, WS_THREADS, WS_SMEM>>>(hh, hl,
            w1h + (size_t)l*dm2, w1l + (size_t)l*dm2,
            b1 + l*DM, nullptr, nullptr, mh, ml, M, DM, D);
        gemm_ws<2><<<gD, WS_THREADS, WS_SMEM>>>(mh, ml,
            w2h + (size_t)l*dm2, w2l + (size_t)l*dm2,
            b2 + l*D, x, x, nullptr, nullptr, M, D, DM);
    }

    ln_split_k<<<M, 256>>>(x, lfg, lfb, hh, hl);
    gemm_ws<0><<<gLM, WS_THREADS, WS_SMEM>>>(hh, hl, wuh, wul,
        bu, nullptr, out, nullptr, nullptr, M, Vn, D);
}

// round 14
// speedup vs baseline: 3.4409x; 1.2622x over previous
#include <cuda_runtime.h>
#include <cuda_bf16.h>
#include <cstdint>
#include <cstddef>

// ---------------- problem constants ----------------
#define BATCH 2
#define TSEQ  1024
#define MROWS (BATCH*TSEQ)      // 2048
#define DMODEL 768
#define NHEAD 12
#define DHEAD 64
#define DMLP  3072
#define NLAYER 12
#define VOCAB 50257
#define DQKV  (3*DMODEL)        // 2304

// ---------------- scratch (static device globals; no allocation) ----------------
__device__ float g_x  [MROWS*DMODEL];          // residual stream (fp32)
__device__ __nv_bfloat16 g_qh[MROWS*DQKV],   g_qlo[MROWS*DQKV];    // qkv split
__device__ __nv_bfloat16 g_hh[MROWS*DMODEL], g_hl[MROWS*DMODEL];   // LN out split
__device__ __nv_bfloat16 g_zh[MROWS*DMODEL], g_zl[MROWS*DMODEL];   // attn out split
__device__ __nv_bfloat16 g_mh[MROWS*DMLP],   g_ml[MROWS*DMLP];     // MLP hidden split

// split+transposed weights, [N][K] K-major bf16 planes
__device__ __nv_bfloat16 g_wqkv_h[NLAYER*DQKV*DMODEL],  g_wqkv_l[NLAYER*DQKV*DMODEL];
__device__ __nv_bfloat16 g_wo_h  [NLAYER*DMODEL*DMODEL],g_wo_l  [NLAYER*DMODEL*DMODEL];
__device__ __nv_bfloat16 g_w1_h  [NLAYER*DMLP*DMODEL],  g_w1_l  [NLAYER*DMLP*DMODEL];
__device__ __nv_bfloat16 g_w2_h  [NLAYER*DMODEL*DMLP],  g_w2_l  [NLAYER*DMODEL*DMLP];
__device__ __nv_bfloat16 g_wu_h  [VOCAB*DMODEL],        g_wu_l  [VOCAB*DMODEL];
__device__ float g_bqkv[NLAYER*DQKV];

// ---------------- PTX helpers (plain sm_80+ features only) ----------------
__device__ __forceinline__ uint32_t smem_u32(const void* p){
    uint32_t a;
    asm("{ .reg .u64 t; cvta.to.shared.u64 t, %1; cvt.u32.u64 %0, t; }" : "=r"(a) : "l"(p));
    return a;
}
__device__ __forceinline__ void cpa16(uint32_t dst, const void* src, uint32_t srcsize){
    asm volatile("cp.async.cg.shared.global [%0], [%1], 16, %2;"
                 :: "r"(dst), "l"(src), "r"(srcsize) : "memory");
}
__device__ __forceinline__ void cpa_commit(){
    asm volatile("cp.async.commit_group;" ::: "memory");
}
__device__ __forceinline__ void cpa_wait1(){
    asm volatile("cp.async.wait_group 1;" ::: "memory");
}
__device__ __forceinline__ void cpa_wait0(){
    asm volatile("cp.async.wait_group 0;" ::: "memory");
}
__device__ __forceinline__ void ldsm4(uint32_t* r, uint32_t addr){
    asm volatile("ldmatrix.sync.aligned.m8n8.x4.shared.b16 {%0,%1,%2,%3}, [%4];"
                 : "=r"(r[0]), "=r"(r[1]), "=r"(r[2]), "=r"(r[3]) : "r"(addr));
}
__device__ __forceinline__ void ldsm4t(uint32_t* r, uint32_t addr){
    asm volatile("ldmatrix.sync.aligned.m8n8.x4.trans.shared.b16 {%0,%1,%2,%3}, [%4];"
                 : "=r"(r[0]), "=r"(r[1]), "=r"(r[2]), "=r"(r[3]) : "r"(addr));
}
__device__ __forceinline__ void mma_bf16(float* c, const uint32_t* a, const uint32_t* b){
    asm volatile("mma.sync.aligned.m16n8k16.row.col.f32.bf16.bf16.f32 "
                 "{%0,%1,%2,%3}, {%4,%5,%6,%7}, {%8,%9}, {%0,%1,%2,%3};"
                 : "+f"(c[0]), "+f"(c[1]), "+f"(c[2]), "+f"(c[3])
                 : "r"(a[0]), "r"(a[1]), "r"(a[2]), "r"(a[3]), "r"(b[0]), "r"(b[1]));
}
#define SMEM_SWIZZLE_128B(o) ((o) ^ (((o) >> 3) & 0x70))

// ---------------- small helpers ----------------
__device__ __forceinline__ float gelu_f(float x){
    return 0.5f * x * (1.0f + erff(x * 0.70710678118654752440f));
}
__device__ __forceinline__ void split2(float v, __nv_bfloat16& h, __nv_bfloat16& l){
    h = __float2bfloat16(v);
    l = __float2bfloat16(v - __bfloat162float(h));
}
__device__ __forceinline__ uint32_t pack_bf16(float a, float b){
    __nv_bfloat162 t = __floats2bfloat162_rn(a, b);   // low = a, high = b
    return *(uint32_t*)&t;
}

// ---------------- uber weight split+transpose (single launch) ----------------
// src[K][N] fp32 -> dst planes [N][K] bf16 (hi/lo), 32x32 tiles
__global__ void tsplit_all(const float* __restrict__ Wq, const float* __restrict__ Wk,
                           const float* __restrict__ Wv, const float* __restrict__ Wo,
                           const float* __restrict__ W1, const float* __restrict__ W2,
                           const float* __restrict__ Wu,
                           __nv_bfloat16* wqh, __nv_bfloat16* wql,
                           __nv_bfloat16* woh, __nv_bfloat16* wol,
                           __nv_bfloat16* w1h, __nv_bfloat16* w1l,
                           __nv_bfloat16* w2h, __nv_bfloat16* w2l,
                           __nv_bfloat16* wuh, __nv_bfloat16* wul)
{
    const int T0 = 24*24*12;          // 6912 tiles per D×D weight
    const int TW = 24*96*12;          // 27648 for W1 / W2
    const int TU = 24*1571;           // 37704 for Wu
    int id = blockIdx.x;
    const float* src; __nv_bfloat16 *dh, *dl;
    long srcLS, dstLS; int rowOff = 0, ld, K, N;
    int l, kti, nti;
    if (id < 4*T0){
        int seg = id / T0, r = id % T0;
        l = r / 576; int r2 = r % 576; kti = r2 / 24; nti = r2 % 24;
        K = 768; N = 768; srcLS = 589824;
        if (seg < 3){
            src = (seg==0)?Wq:(seg==1)?Wk:Wv;
            dh = wqh; dl = wql; dstLS = 1769472; ld = 768; rowOff = seg*768;
        } else {
            src = Wo; dh = woh; dl = wol; dstLS = 589824; ld = 768;
        }
    } else if (id < 4*T0 + TW){
        int r = id - 4*T0;
        l = r / 2304; int r2 = r % 2304; kti = r2 / 96; nti = r2 % 96;
        src = W1; dh = w1h; dl = w1l; srcLS = 2359296; dstLS = 2359296;
        ld = 768; K = 768; N = 3072;
    } else if (id < 4*T0 + 2*TW){
        int r = id - 4*T0 - TW;
        l = r / 2304; int r2 = r % 2304; kti = r2 / 24; nti = r2 % 24;
        src = W2; dh = w2h; dl = w2l; srcLS = 2359296; dstLS = 2359296;
        ld = 3072; K = 3072; N = 768;
    } else {
        int r = id - 4*T0 - 2*TW;
        l = 0; kti = r / 1571; nti = r % 1571;
        src = Wu; dh = wuh; dl = wul; srcLS = 0; dstLS = 0;
        ld = 768; K = 768; N = VOCAB;
    }
    const int k0 = kti*32, n0 = nti*32;
    __shared__ float t[32][33];
    int tx = threadIdx.x & 31, ty = threadIdx.x >> 5;
    const float* s = src + (size_t)l * srcLS;
    #pragma unroll
    for (int i = ty; i < 32; i += 8){
        int k = k0 + i, n = n0 + tx;
        t[i][tx] = (k < K && n < N) ? s[(size_t)k * N + n] : 0.f;
    }
    __syncthreads();
    __nv_bfloat16* ph = dh + (size_t)l * dstLS;
    __nv_bfloat16* pl = dl + (size_t)l * dstLS;
    #pragma unroll
    for (int i = ty; i < 32; i += 8){
        int n = n0 + i, k = k0 + tx;
        if (n < N && k < K){
            float v = t[tx][i];
            __nv_bfloat16 h, lo; split2(v, h, lo);
            size_t off = (size_t)(rowOff + n) * ld + k;
            ph[off] = h; pl[off] = lo;
        }
    }
}

__global__ void bcat_k(const float* __restrict__ bq, const float* __restrict__ bk,
                       const float* __restrict__ bv, float* __restrict__ dst)
{
    int l = blockIdx.y;
    int i = blockIdx.x * 256 + threadIdx.x;
    if (i < DQKV){
        float v = (i < 768) ? bq[l*768 + i] : (i < 1536) ? bk[l*768 + i - 768]
                                                         : bv[l*768 + i - 1536];
        dst[l*DQKV + i] = v;
    }
}

// ---------------- embedding ----------------
__global__ void embed_k(const int* __restrict__ ids, const float* __restrict__ emb,
                        const float* __restrict__ pos, float* __restrict__ x)
{
    int row = blockIdx.x, t = row % TSEQ, id = ids[row];
    const float* er = emb + (size_t)id * DMODEL;
    const float* pr = pos + (size_t)t  * DMODEL;
    float* xr = x + (size_t)row * DMODEL;
    int tid = threadIdx.x;
    xr[tid]       = er[tid]       + pr[tid];
    xr[tid + 256] = er[tid + 256] + pr[tid + 256];
    xr[tid + 512] = er[tid + 512] + pr[tid + 512];
}

// ---------------- layernorm -> bf16 hi/lo split ----------------
__global__ void ln_split_k(const float* __restrict__ x, const float* __restrict__ g,
                           const float* __restrict__ b,
                           __nv_bfloat16* __restrict__ oh, __nv_bfloat16* __restrict__ ol)
{
    __shared__ float red0[8], red1[8];
    int row = blockIdx.x, tid = threadIdx.x;
    const float* xr = x + (size_t)row * DMODEL;
    float v0 = xr[tid], v1 = xr[tid + 256], v2 = xr[tid + 512];
    float s  = v0 + v1 + v2;
    float s2 = v0*v0 + v1*v1 + v2*v2;
    #pragma unroll
    for (int off = 16; off; off >>= 1){
        s  += __shfl_xor_sync(0xffffffffu, s,  off);
        s2 += __shfl_xor_sync(0xffffffffu, s2, off);
    }
    int w = tid >> 5;
    if ((tid & 31) == 0){ red0[w] = s; red1[w] = s2; }
    __syncthreads();
    if (tid < 32){
        s  = (tid < 8) ? red0[tid] : 0.f;
        s2 = (tid < 8) ? red1[tid] : 0.f;
        #pragma unroll
        for (int off = 4; off; off >>= 1){
            s  += __shfl_xor_sync(0xffffffffu, s,  off);
            s2 += __shfl_xor_sync(0xffffffffu, s2, off);
        }
        if (tid == 0){ red0[0] = s; red1[0] = s2; }
    }
    __syncthreads();
    float mean = red0[0] * (1.f/768.f);
    float var  = red1[0] * (1.f/768.f) - mean * mean;
    float r    = rsqrtf(var + 1e-5f);
    size_t base = (size_t)row * DMODEL;
    #pragma unroll
    for (int e = 0; e < 3; ++e){
        int idx = tid + e*256;
        float vv = (e==0?v0:(e==1?v1:v2));
        float y = (vv - mean) * r * g[idx] + b[idx];
        __nv_bfloat16 h, lo; split2(y, h, lo);
        oh[base + idx] = h; ol[base + idx] = lo;
    }
}

// ---------------- mma.sync bf16-split GEMM ----------------
// C[M,N] = epi( (Ah+Al) * (Bh+Bl)^T + bias )   A:[M][K] planes, B:[N][K] planes.
// EPI: 0 = fp32 out ; 2 = fp32 out + residual ; 3 = GELU -> bf16 split out ;
//      4 = bias only -> bf16 split out
#define WS_THREADS 256
#define WS_NSTAGE 3
#define WS_STAGE_BYTES 65536
#define WS_SMEM (WS_NSTAGE*WS_STAGE_BYTES)

template<int EPI>
__global__ __launch_bounds__(WS_THREADS, 1)
void gemm_ws(const __nv_bfloat16* __restrict__ Ah, const __nv_bfloat16* __restrict__ Al,
             const __nv_bfloat16* __restrict__ Bh, const __nv_bfloat16* __restrict__ Bl,
             const float* __restrict__ bias, const float* __restrict__ res,
             float* __restrict__ C, __nv_bfloat16* __restrict__ Ch,
             __nv_bfloat16* __restrict__ Cl, int M, int N, int K)
{
    extern __shared__ char smem[];
    const uint32_t sb = smem_u32(smem);
    const int tid = threadIdx.x, wid = tid >> 5, lane = tid & 31;
    const int warp_m = wid & 1;
    const int warp_n = wid >> 1;
    const int m0 = blockIdx.y * 128, n0 = blockIdx.x * 128;

    float acc[16][4];
    #pragma unroll
    for (int i = 0; i < 16; i++)
        #pragma unroll
        for (int j = 0; j < 4; j++) acc[i][j] = 0.f;

    const int nch = K >> 6;

    auto load_stage = [&](int st, int k0){
        const uint32_t s0 = sb + (uint32_t)st * WS_STAGE_BYTES;
        #pragma unroll
        for (int it = 0; it < 4; ++it){
            int idx = it * 256 + tid;
            int row = idx >> 3, ch = idx & 7;
            uint32_t off = SMEM_SWIZZLE_128B(row*128 + ch*16);
            const size_t aoff = (size_t)(m0 + row) * K + k0 + ch*8;
            cpa16(s0 +         off, Ah + aoff, 16);
            cpa16(s0 + 16384 + off, Al + aoff, 16);
            int brow = n0 + row;
            uint32_t sz = (brow < N) ? 16u : 0u;
            if (brow >= N) brow = N - 1;
            const size_t boff = (size_t)brow * K + k0 + ch*8;
            cpa16(s0 + 32768 + off, Bh + boff, sz);
            cpa16(s0 + 49152 + off, Bl + boff, sz);
        }
        cpa_commit();
    };

    auto compute_stage = [&](int st){
        const uint32_t sAh = sb + (uint32_t)st * WS_STAGE_BYTES;
        const uint32_t sAl = sAh + 16384;
        const uint32_t sBh = sAh + 32768;
        const uint32_t sBl = sAh + 49152;
        #pragma unroll
        for (int ks = 0; ks < 4; ++ks){
            uint32_t ah[4][4], al[4][4], bh[4][2], bl[4][2];
            const int arow = warp_m*64 + (lane & 7) + ((lane >> 3) & 1) * 8;
            const int akc  = ks*16 + ((lane >> 4) & 1) * 8;
            #pragma unroll
            for (int mt = 0; mt < 4; ++mt){
                uint32_t off = SMEM_SWIZZLE_128B((arow + mt*16)*128 + akc*2);
                ldsm4(ah[mt], sAh + off);
                ldsm4(al[mt], sAl + off);
            }
            const int brow0 = warp_n*32 + ((lane >> 4) & 1) * 8 + (lane & 7);
            const int bkc   = ks*16 + ((lane >> 3) & 1) * 8;
            #pragma unroll
            for (int nq = 0; nq < 2; ++nq){
                uint32_t off = SMEM_SWIZZLE_128B((brow0 + nq*16)*128 + bkc*2);
                uint32_t r[4];
                ldsm4(r, sBh + off);
                bh[2*nq][0] = r[0]; bh[2*nq][1] = r[1];
                bh[2*nq+1][0] = r[2]; bh[2*nq+1][1] = r[3];
                ldsm4(r, sBl + off);
                bl[2*nq][0] = r[0]; bl[2*nq][1] = r[1];
                bl[2*nq+1][0] = r[2]; bl[2*nq+1][1] = r[3];
            }
            #pragma unroll
            for (int mt = 0; mt < 4; ++mt)
                #pragma unroll
                for (int nt = 0; nt < 4; ++nt){
                    float* c = acc[mt*4 + nt];
                    mma_bf16(c, ah[mt], bh[nt]);
                    mma_bf16(c, ah[mt], bl[nt]);
                    mma_bf16(c, al[mt], bh[nt]);
                }
        }
    };

    load_stage(0, 0);
    load_stage(1, 64);
    for (int c = 0; c < nch; ++c){
        if (c + 1 < nch) cpa_wait1(); else cpa_wait0();
        __syncthreads();
        int p = c + WS_NSTAGE - 1;
        if (p < nch) load_stage(p % WS_NSTAGE, p * 64);
        else cpa_commit();
        compute_stage(c % WS_NSTAGE);
    }

    const int lr = lane >> 2, lc = (lane & 3) * 2;
    const bool nvec = ((N & 1) == 0);
    #pragma unroll
    for (int mt = 0; mt < 4; ++mt){
        #pragma unroll
        for (int nt = 0; nt < 4; ++nt){
            const float* cfr = acc[mt*4 + nt];
            const int n = n0 + warp_n*32 + nt*8 + lc;
            #pragma unroll
            for (int half = 0; half < 2; ++half){
                const int m = m0 + warp_m*64 + mt*16 + lr + half*8;
                float v0 = cfr[half*2 + 0];
                float v1 = cfr[half*2 + 1];
                if (EPI == 3 || EPI == 4){
                    v0 += bias[n]; v1 += bias[n+1];
                    if (EPI == 3){ v0 = gelu_f(v0); v1 = gelu_f(v1); }
                    __nv_bfloat16 h0, l0, h1, l1;
                    split2(v0, h0, l0); split2(v1, h1, l1);
                    __nv_bfloat162 hp; hp.x = h0; hp.y = h1;
                    __nv_bfloat162 lp; lp.x = l0; lp.y = l1;
                    *(__nv_bfloat162*)(Ch + (size_t)m * N + n) = hp;
                    *(__nv_bfloat162*)(Cl + (size_t)m * N + n) = lp;
                } else {
                    if (n < N) v0 += bias[n];
                    if (n + 1 < N) v1 += bias[n+1];
                    if (EPI == 2){
                        const float2 r2 = *(const float2*)(res + (size_t)m * N + n);
                        v0 += r2.x; v1 += r2.y;
                    }
                    if (nvec && (n + 1 < N)){
                        float2 o2; o2.x = v0; o2.y = v1;
                        *(float2*)(C + (size_t)m * N + n) = o2;
                    } else {
                        if (n < N)     C[(size_t)m * N + n]     = v0;
                        if (n + 1 < N) C[(size_t)m * N + n + 1] = v1;
                    }
                }
            }
        }
    }
}

// ---------------- tensor-core flash attention (bf16 hi/lo split, 3-pass) ----------------
// Input: qkv planes [M][2304] (hi/lo). Output: Z planes [M][768] (hi/lo).
// CTA: 64 q rows, 4 warps x 16 rows. KV tiles of 64. smem = 48KB.
#define AT_SMEM 49152
__global__ __launch_bounds__(128)
void attn_tc(const __nv_bfloat16* __restrict__ Xh, const __nv_bfloat16* __restrict__ Xl,
             __nv_bfloat16* __restrict__ Zh, __nv_bfloat16* __restrict__ Zl)
{
    extern __shared__ char sm[];
    const uint32_t sb = smem_u32(sm);
    // layout: Qh 0, Ql 8192, Kh 16384, Kl 24576, Vh 32768, Vl 40960
    const int tid = threadIdx.x, warp = tid >> 5, lane = tid & 31;
    const int qt = blockIdx.x, bh = blockIdx.y;
    const int b = bh / NHEAD, h = bh % NHEAD;
    const int q0 = qt * 64;
    const size_t rowbase = (size_t)b * TSEQ;
    const int colQ = h*DHEAD, colK = DMODEL + h*DHEAD, colV = 2*DMODEL + h*DHEAD;

    // load Q tile (hi/lo)
    #pragma unroll
    for (int it = 0; it < 4; ++it){
        int idx = it*128 + tid;
        int r = idx >> 3, ch = idx & 7;
        uint32_t off = SMEM_SWIZZLE_128B(r*128 + ch*16);
        size_t go = (rowbase + q0 + r) * (size_t)DQKV + colQ + ch*8;
        cpa16(sb +        off, Xh + go, 16);
        cpa16(sb + 8192 + off, Xl + go, 16);
    }
    cpa_commit();

    float mst[2] = {-1e30f, -1e30f}, lst[2] = {0.f, 0.f};
    float zacc[8][4];
    #pragma unroll
    for (int j = 0; j < 8; j++)
        #pragma unroll
        for (int i = 0; i < 4; i++) zacc[j][i] = 0.f;

    cpa_wait0();
    __syncthreads();

    // Q fragments (A operand), 4 k16 slices, hi/lo
    uint32_t qh[4][4], ql[4][4];
    {
        const int arow = warp*16 + (lane & 7) + ((lane >> 3) & 1) * 8;
        #pragma unroll
        for (int ks = 0; ks < 4; ++ks){
            int akc = ks*16 + ((lane >> 4) & 1) * 8;
            uint32_t off = SMEM_SWIZZLE_128B(arow*128 + akc*2);
            ldsm4(qh[ks], sb +        off);
            ldsm4(ql[ks], sb + 8192 + off);
        }
    }

    const int nkt = qt + 1;
    for (int kt = 0; kt < nkt; ++kt){
        const int k0 = kt * 64;
        __syncthreads();          // previous tile's ldsm reads done
        #pragma unroll
        for (int it = 0; it < 4; ++it){
            int idx = it*128 + tid;
            int r = idx >> 3, ch = idx & 7;
            uint32_t off = SMEM_SWIZZLE_128B(r*128 + ch*16);
            size_t gk = (rowbase + k0 + r) * (size_t)DQKV + colK + ch*8;
            size_t gv = (rowbase + k0 + r) * (size_t)DQKV + colV + ch*8;
            cpa16(sb + 16384 + off, Xh + gk, 16);
            cpa16(sb + 24576 + off, Xl + gk, 16);
            cpa16(sb + 32768 + off, Xh + gv, 16);
            cpa16(sb + 40960 + off, Xl + gv, 16);
        }
        cpa_commit(); cpa_wait0();
        __syncthreads();

        // ---- S = Q K^T (3-pass split), per warp: 16 x 64 ----
        float sacc[8][4];
        #pragma unroll
        for (int j = 0; j < 8; j++)
            #pragma unroll
            for (int i = 0; i < 4; i++) sacc[j][i] = 0.f;

        #pragma unroll
        for (int ks = 0; ks < 4; ++ks){
            uint32_t bhf[8][2], blf[8][2];
            const int brow = ((lane >> 4) & 1) * 8 + (lane & 7);
            const int bkc  = ks*16 + ((lane >> 3) & 1) * 8;
            #pragma unroll
            for (int nq = 0; nq < 4; ++nq){
                uint32_t off = SMEM_SWIZZLE_128B((nq*16 + brow)*128 + bkc*2);
                uint32_t r[4];
                ldsm4(r, sb + 16384 + off);
                bhf[2*nq][0] = r[0]; bhf[2*nq][1] = r[1];
                bhf[2*nq+1][0] = r[2]; bhf[2*nq+1][1] = r[3];
                ldsm4(r, sb + 24576 + off);
                blf[2*nq][0] = r[0]; blf[2*nq][1] = r[1];
                blf[2*nq+1][0] = r[2]; blf[2*nq+1][1] = r[3];
            }
            #pragma unroll
            for (int j = 0; j < 8; j++){
                mma_bf16(sacc[j], qh[ks], bhf[j]);
                mma_bf16(sacc[j], qh[ks], blf[j]);
                mma_bf16(sacc[j], ql[ks], bhf[j]);
            }
        }

        // ---- scale + causal mask ----
        const bool diag = (kt == qt);
        const int r0g = q0 + warp*16 + (lane >> 2);
        #pragma unroll
        for (int j = 0; j < 8; j++){
            const int kg = k0 + j*8 + (lane & 3)*2;
            #pragma unroll
            for (int i = 0; i < 4; i++){
                float v = sacc[j][i] * 0.125f;
                if (diag){
                    int kk = kg + (i & 1);
                    int qq = r0g + ((i >= 2) ? 8 : 0);
                    if (kk > qq) v = -1e30f;
                }
                sacc[j][i] = v;
            }
        }

        // ---- online softmax (rows r0, r0+8; reduce over 4-lane col groups) ----
        #pragma unroll
        for (int t = 0; t < 2; ++t){
            float mx = -1e30f;
            #pragma unroll
            for (int j = 0; j < 8; j++)
                mx = fmaxf(mx, fmaxf(sacc[j][2*t], sacc[j][2*t+1]));
            mx = fmaxf(mx, __shfl_xor_sync(0xffffffffu, mx, 1));
            mx = fmaxf(mx, __shfl_xor_sync(0xffffffffu, mx, 2));
            float mn = fmaxf(mst[t], mx);
            float corr = expf(mst[t] - mn);
            mst[t] = mn;
            float rs = 0.f;
            #pragma unroll
            for (int j = 0; j < 8; j++){
                float p0 = expf(sacc[j][2*t]   - mn);
                float p1 = expf(sacc[j][2*t+1] - mn);
                sacc[j][2*t] = p0; sacc[j][2*t+1] = p1;
                rs += p0 + p1;
            }
            rs += __shfl_xor_sync(0xffffffffu, rs, 1);
            rs += __shfl_xor_sync(0xffffffffu, rs, 2);
            lst[t] = lst[t] * corr + rs;
            #pragma unroll
            for (int j = 0; j < 8; j++){
                zacc[j][2*t]   *= corr;
                zacc[j][2*t+1] *= corr;
            }
        }

        // ---- Z += P V  (P split in registers, V via ldsm.trans; 3-pass) ----
        #pragma unroll
        for (int ks2 = 0; ks2 < 4; ++ks2){
            // P fragments from sacc (C-layout -> A-layout identity)
            uint32_t ph[4], pl[4];
            {
                const float* s0 = sacc[2*ks2];
                const float* s1 = sacc[2*ks2+1];
                __nv_bfloat162 h0 = __floats2bfloat162_rn(s0[0], s0[1]);
                __nv_bfloat162 h1 = __floats2bfloat162_rn(s0[2], s0[3]);
                __nv_bfloat162 h2 = __floats2bfloat162_rn(s1[0], s1[1]);
                __nv_bfloat162 h3 = __floats2bfloat162_rn(s1[2], s1[3]);
                ph[0] = *(uint32_t*)&h0; ph[1] = *(uint32_t*)&h1;
                ph[2] = *(uint32_t*)&h2; ph[3] = *(uint32_t*)&h3;
                pl[0] = pack_bf16(s0[0] - __bfloat162float(h0.x), s0[1] - __bfloat162float(h0.y));
                pl[1] = pack_bf16(s0[2] - __bfloat162float(h1.x), s0[3] - __bfloat162float(h1.y));
                pl[2] = pack_bf16(s1[0] - __bfloat162float(h2.x), s1[1] - __bfloat162float(h2.y));
                pl[3] = pack_bf16(s1[2] - __bfloat162float(h3.x), s1[3] - __bfloat162float(h3.y));
            }
            // V fragments (B operand, n=d, k=kv) via trans loads from Vs[kv][d]
            uint32_t vh[8][2], vl[8][2];
            const int vrow = ks2*16 + ((lane >> 3) & 1) * 8 + (lane & 7);
            const int vcb  = ((lane >> 4) & 1) * 8;
            #pragma unroll
            for (int nq = 0; nq < 4; ++nq){
                uint32_t off = SMEM_SWIZZLE_128B(vrow*128 + (nq*16 + vcb)*2);
                uint32_t r[4];
                ldsm4t(r, sb + 32768 + off);
                vh[2*nq][0] = r[0]; vh[2*nq][1] = r[1];
                vh[2*nq+1][0] = r[2]; vh[2*nq+1][1] = r[3];
                ldsm4t(r, sb + 40960 + off);
                vl[2*nq][0] = r[0]; vl[2*nq][1] = r[1];
                vl[2*nq+1][0] = r[2]; vl[2*nq+1][1] = r[3];
            }
            #pragma unroll
            for (int j = 0; j < 8; j++){
                mma_bf16(zacc[j], ph, vh[j]);
                mma_bf16(zacc[j], ph, vl[j]);
                mma_bf16(zacc[j], pl, vh[j]);
            }
        }
    }

    // ---- normalize + write Z as bf16 hi/lo planes [M][768] ----
    #pragma unroll
    for (int t = 0; t < 2; ++t){
        float inv = 1.f / lst[t];
        int qg = q0 + warp*16 + (lane >> 2) + t*8;
        size_t ob = (rowbase + qg) * (size_t)DMODEL + h*DHEAD;
        #pragma unroll
        for (int j = 0; j < 8; j++){
            int d = j*8 + (lane & 3)*2;
            float z0 = zacc[j][2*t]   * inv;
            float z1 = zacc[j][2*t+1] * inv;
            __nv_bfloat16 h0, l0, h1, l1;
            split2(z0, h0, l0); split2(z1, h1, l1);
            __nv_bfloat162 hp; hp.x = h0; hp.y = h1;
            __nv_bfloat162 lp; lp.x = l0; lp.y = l1;
            *(__nv_bfloat162*)(Zh + ob + d) = hp;
            *(__nv_bfloat162*)(Zl + ob + d) = lp;
        }
    }
}

// ---------------- host orchestration ----------------
extern "C" void kernel_launch(void* const* d_in, const int* in_sizes, int n_in,
                              void* d_out, int out_size)
{
    const int*   ids = (const int*)  d_in[0];
    const float* emb = (const float*)d_in[1];
    const float* pos = (const float*)d_in[2];
    const float* Wq  = (const float*)d_in[3],  *bq = (const float*)d_in[4];
    const float* Wk  = (const float*)d_in[5],  *bk = (const float*)d_in[6];
    const float* Wv  = (const float*)d_in[7],  *bv = (const float*)d_in[8];
    const float* Wo  = (const float*)d_in[9],  *bo = (const float*)d_in[10];
    const float* l1g = (const float*)d_in[11], *l1b = (const float*)d_in[12];
    const float* l2g = (const float*)d_in[13], *l2b = (const float*)d_in[14];
    const float* W1  = (const float*)d_in[15], *b1 = (const float*)d_in[16];
    const float* W2  = (const float*)d_in[17], *b2 = (const float*)d_in[18];
    const float* lfg = (const float*)d_in[19], *lfb = (const float*)d_in[20];
    const float* Wu  = (const float*)d_in[21], *bu = (const float*)d_in[22];
    float* out = (float*)d_out;

    float *x, *bqkv;
    __nv_bfloat16 *qh, *qlo, *hh, *hl, *zh, *zl, *mh, *ml;
    __nv_bfloat16 *wqh, *wql, *woh, *wol, *w1h, *w1l, *w2h, *w2l, *wuh, *wul;
    cudaGetSymbolAddress((void**)&x,    g_x);
    cudaGetSymbolAddress((void**)&bqkv, g_bqkv);
    cudaGetSymbolAddress((void**)&qh,   g_qh);  cudaGetSymbolAddress((void**)&qlo, g_qlo);
    cudaGetSymbolAddress((void**)&hh,   g_hh);  cudaGetSymbolAddress((void**)&hl, g_hl);
    cudaGetSymbolAddress((void**)&zh,   g_zh);  cudaGetSymbolAddress((void**)&zl, g_zl);
    cudaGetSymbolAddress((void**)&mh,   g_mh);  cudaGetSymbolAddress((void**)&ml, g_ml);
    cudaGetSymbolAddress((void**)&wqh,  g_wqkv_h); cudaGetSymbolAddress((void**)&wql, g_wqkv_l);
    cudaGetSymbolAddress((void**)&woh,  g_wo_h);   cudaGetSymbolAddress((void**)&wol, g_wo_l);
    cudaGetSymbolAddress((void**)&w1h,  g_w1_h);   cudaGetSymbolAddress((void**)&w1l, g_w1_l);
    cudaGetSymbolAddress((void**)&w2h,  g_w2_h);   cudaGetSymbolAddress((void**)&w2l, g_w2_l);
    cudaGetSymbolAddress((void**)&wuh,  g_wu_h);   cudaGetSymbolAddress((void**)&wul, g_wu_l);

    cudaFuncSetAttribute(gemm_ws<0>, cudaFuncAttributeMaxDynamicSharedMemorySize, WS_SMEM);
    cudaFuncSetAttribute(gemm_ws<2>, cudaFuncAttributeMaxDynamicSharedMemorySize, WS_SMEM);
    cudaFuncSetAttribute(gemm_ws<3>, cudaFuncAttributeMaxDynamicSharedMemorySize, WS_SMEM);
    cudaFuncSetAttribute(gemm_ws<4>, cudaFuncAttributeMaxDynamicSharedMemorySize, WS_SMEM);
    cudaFuncSetAttribute(attn_tc,    cudaFuncAttributeMaxDynamicSharedMemorySize, AT_SMEM);

    const int M = MROWS, D = DMODEL, DM = DMLP, Vn = VOCAB;
    const size_t d2 = (size_t)D * D, dm2 = (size_t)D * DM;

    // single-launch weight split (tiles: 4*6912 + 2*27648 + 37704 = 120648)
    tsplit_all<<<120648, 256>>>(Wq, Wk, Wv, Wo, W1, W2, Wu,
                                wqh, wql, woh, wol, w1h, w1l, w2h, w2l, wuh, wul);
    bcat_k<<<dim3((DQKV + 255)/256, NLAYER), 256>>>(bq, bk, bv, bqkv);
    embed_k<<<M, 256>>>(ids, emb, pos, x);

    const dim3 gQKV(DQKV/128, M/128);      // (18,16)
    const dim3 gD  (D/128,    M/128);      // (6,16)
    const dim3 gM1 (DM/128,   M/128);      // (24,16)
    const dim3 gLM ((Vn + 127)/128, M/128);

    for (int l = 0; l < NLAYER; ++l){
        ln_split_k<<<M, 256>>>(x, l1g + l*D, l1b + l*D, hh, hl);
        gemm_ws<4><<<gQKV, WS_THREADS, WS_SMEM>>>(hh, hl,
            wqh + (size_t)l*DQKV*D, wql + (size_t)l*DQKV*D,
            bqkv + l*DQKV, nullptr, nullptr, qh, qlo, M, DQKV, D);
        attn_tc<<<dim3(TSEQ/64, BATCH*NHEAD), 128, AT_SMEM>>>(qh, qlo, zh, zl);
        gemm_ws<2><<<gD, WS_THREADS, WS_SMEM>>>(zh, zl,
            woh + (size_t)l*d2, wol + (size_t)l*d2,
            bo + l*D, x, x, nullptr, nullptr, M, D, D);
        ln_split_k<<<M, 256>>>(x, l2g + l*D, l2b + l*D, hh, hl);
        gemm_ws<3><<<gM1, WS_THREADS, WS_SMEM>>>(hh, hl,
            w1h + (size_t)l*dm2, w1l + (size_t)l*dm2,
            b1 + l*DM, nullptr, nullptr, mh, ml, M, DM, D);
        gemm_ws<2><<<gD, WS_THREADS, WS_SMEM>>>(mh, ml,
            w2h + (size_t)l*dm2, w2l + (size_t)l*dm2,
            b2 + l*D, x, x, nullptr, nullptr, M, D, DM);
    }

    ln_split_k<<<M, 256>>>(x, lfg, lfb, hh, hl);
    gemm_ws<0><<<gLM, WS_THREADS, WS_SMEM>>>(hh, hl, wuh, wul,
        bu, nullptr, out, nullptr, nullptr, M, Vn, D);
}